// round 12
// baseline (speedup 1.0000x reference)
#include <cuda_runtime.h>
#include <cuda_fp16.h>
#include <cstdint>

// Problem constants
#define BB 2
#define LL 2048
#define DD 1024
#define HH 16
#define HD 64
#define NQKV 3072        // 3*H*HD
#define MROWS (BB*LL)    // 4096

// ---------------- scratch (device globals; no allocations allowed) -------
__device__ __half g_xf[MROWS * DD];               // x single fp16
__device__ __half g_wqkvT[NQKV * DD];             // [N][K] single
__device__ __half g_woutT[DD * DD];               // [N][K] single

// attention operands, fp16 single, [B,H,L,HD] (Q scaled by 0.125*log2e)
__device__ __half g_Qf[BB * HH * LL * HD];
__device__ __half g_Kf[BB * HH * LL * HD];
__device__ __half g_Vf[BB * HH * LL * HD];
__device__ __half g_attf[MROWS * DD];             // [B*L, 1024] single

// ==================== helpers =============================================
__device__ __forceinline__ uint32_t smem_u32(const void* p) {
    uint32_t a;
    asm("{ .reg .u64 t; cvta.to.shared.u64 t, %1; cvt.u32.u64 %0, t; }"
        : "=r"(a) : "l"(p));
    return a;
}

// pack two floats -> half2 reg (a in low half)
__device__ __forceinline__ uint32_t pack2h(float a, float b) {
    __half2 h = __floats2half2_rn(a, b);
    return *(uint32_t*)&h;
}

__device__ __forceinline__ void ldsm4(uint32_t* r, uint32_t addr) {
    asm volatile("ldmatrix.sync.aligned.m8n8.x4.shared.b16 {%0,%1,%2,%3}, [%4];"
                 : "=r"(r[0]), "=r"(r[1]), "=r"(r[2]), "=r"(r[3]) : "r"(addr));
}

__device__ __forceinline__ void ldsm4t(uint32_t* r, uint32_t addr) {
    asm volatile("ldmatrix.sync.aligned.m8n8.x4.trans.shared.b16 {%0,%1,%2,%3}, [%4];"
                 : "=r"(r[0]), "=r"(r[1]), "=r"(r[2]), "=r"(r[3]) : "r"(addr));
}

__device__ __forceinline__ void mma_f16(float* d, const uint32_t* a, uint32_t b0, uint32_t b1) {
    asm volatile(
        "mma.sync.aligned.m16n8k16.row.col.f32.f16.f16.f32 "
        "{%0,%1,%2,%3}, {%4,%5,%6,%7}, {%8,%9}, {%0,%1,%2,%3};"
        : "+f"(d[0]), "+f"(d[1]), "+f"(d[2]), "+f"(d[3])
        : "r"(a[0]), "r"(a[1]), "r"(a[2]), "r"(a[3]), "r"(b0), "r"(b1));
}

// cp.async with L1 caching (.ca)
__device__ __forceinline__ void cpa16(uint32_t dst, const void* src) {
    asm volatile("cp.async.ca.shared.global [%0], [%1], 16;" :: "r"(dst), "l"(src));
}
#define CP_COMMIT() asm volatile("cp.async.commit_group;" ::: "memory")
#define CP_WAIT0()  asm volatile("cp.async.wait_group 0;" ::: "memory")
#define CP_WAIT1()  asm volatile("cp.async.wait_group 1;" ::: "memory")

// fast exp2 on FMA pipe (x <= 0 expected; clamped at -120)
__device__ __forceinline__ float fexp2(float x) {
    x = fmaxf(x, -120.0f);
    float n = floorf(x);
    float f = x - n;
    float p = 1.5404226e-4f;
    p = fmaf(p, f, 1.3333558e-3f);
    p = fmaf(p, f, 9.6181291e-3f);
    p = fmaf(p, f, 5.5504109e-2f);
    p = fmaf(p, f, 2.4022651e-1f);
    p = fmaf(p, f, 6.9314718e-1f);
    p = fmaf(p, f, 1.0f);
    return __int_as_float(__float_as_int(p) + (((int)n) << 23));
}

// ==================== conversion kernels ==================================
__global__ void conv_half(const float* __restrict__ src,
                          __half* __restrict__ dst, int n4)
{
    const int i = blockIdx.x * blockDim.x + threadIdx.x;
    if (i >= n4) return;
    float4 v = ((const float4*)src)[i];
    __half h[4];
    h[0] = __float2half_rn(v.x);
    h[1] = __float2half_rn(v.y);
    h[2] = __float2half_rn(v.z);
    h[3] = __float2half_rn(v.w);
    ((uint2*)dst)[i] = *(uint2*)h;
}

// W[K][N] fp32 -> T [N][K] single fp16 (transpose)
__global__ void conv_halfT(const float* __restrict__ W,
                           __half* __restrict__ T,
                           int Kdim, int Ndim)
{
    __shared__ float t[32][33];
    const int tx = threadIdx.x, ty = threadIdx.y;
    const int nb = blockIdx.x * 32;
    const int kb = blockIdx.y * 32;
    #pragma unroll
    for (int i = 0; i < 4; i++)
        t[ty + i * 8][tx] = W[(size_t)(kb + ty + i * 8) * Ndim + nb + tx];
    __syncthreads();
    #pragma unroll
    for (int i = 0; i < 4; i++) {
        const float v = t[tx][ty + i * 8];
        T[(size_t)(nb + ty + i * 8) * Kdim + kb + tx] = __float2half_rn(v);
    }
}

// ============= GEMM: CTA 128Mx256N, warp 64Mx64N, 3-stage ring ============
#define GBM 128
#define GBN 256
#define GBK 32
#define SROW 20                       // padded row stride (u32) = 80B
#define AOP  (GBM * SROW * 4)         // A buffer: 10240 B
#define BOP  (GBN * SROW * 4)         // B buffer: 20480 B
#define GA   0                        // A (3 buffers)
#define GB   (3 * AOP)                // W (3 buffers)
#define GEMM_SMEM (3 * AOP + 3 * BOP) // 92160 B

struct GemmCtx {
    uint32_t sb;
    int warpM, warpN, lane;
    int mBase, nBase;
};

// acc layout: acc[mt 0..3][n8 0..7][4]
__device__ __forceinline__ void gemm_mainloop(
    const GemmCtx& g, const __half* Afg, const __half* Bg,
    int K, int tid, float acc[4][8][4])
{
    const int rowA = tid >> 1;
    const int segA = tid & 1;
    const uint32_t soA = (rowA * SROW + segA * 8) * 4;
    const uint32_t soB = tid * SROW * 4;
    const int nchunks = K / GBK;
    const uint32_t lrow = g.lane & 15;
    const uint32_t lhi  = (g.lane >> 4) << 4;

    auto stage = [&](int c, int buf) {
        const int k0 = c * GBK;
        const size_t ga = (size_t)(g.mBase + rowA) * K + k0 + segA * 16;
        const size_t gb = (size_t)(g.nBase + tid) * K + k0;
        cpa16(g.sb + GA + buf * AOP + soA,      Afg + ga);
        cpa16(g.sb + GA + buf * AOP + soA + 16, Afg + ga + 8);
        const uint32_t db = g.sb + GB + buf * BOP + soB;
        cpa16(db,      Bg + gb);
        cpa16(db + 16, Bg + gb + 8);
        cpa16(db + 32, Bg + gb + 16);
        cpa16(db + 48, Bg + gb + 24);
    };

    stage(0, 0); CP_COMMIT();
    stage(1, 1); CP_COMMIT();

    for (int c = 0; c < nchunks; c++) {
        if (c + 1 < nchunks) { CP_WAIT1(); } else { CP_WAIT0(); }
        __syncthreads();

        const uint32_t bA = g.sb + GA + (c % 3) * AOP;
        const uint32_t bB = g.sb + GB + (c % 3) * BOP;

        #pragma unroll
        for (int ks = 0; ks < 2; ks++) {
            const uint32_t kboff = ks * 32 + lhi;
            uint32_t ah[4][4];
            uint32_t bf[4][4];
            #pragma unroll
            for (int mt = 0; mt < 4; mt++) {
                const uint32_t ro = (g.warpM * 64 + mt * 16 + lrow) * (SROW * 4) + kboff;
                ldsm4(ah[mt], bA + ro);
            }
            #pragma unroll
            for (int reg = 0; reg < 4; reg++) {
                const uint32_t ro = (g.warpN * 64 + reg * 16 + lrow) * (SROW * 4) + kboff;
                ldsm4(bf[reg], bB + ro);
            }
            #pragma unroll
            for (int reg = 0; reg < 4; reg++)
                #pragma unroll
                for (int mt = 0; mt < 4; mt++)
                    #pragma unroll
                    for (int t = 0; t < 2; t++)
                        mma_f16(acc[mt][reg * 2 + t], ah[mt], bf[reg][t], bf[reg][t + 2]);
        }

        if (c + 2 < nchunks) { stage(c + 2, (c + 2) % 3); CP_COMMIT(); }
    }
}

// ---- QKV GEMM with fused RoPE epilogue: Q/K/V single fp16 ---------------
__global__ __launch_bounds__(256, 1)
void mma_gemm_qkv(const __half* __restrict__ Afg, const __half* __restrict__ Bg,
                  const float* __restrict__ cosT, const float* __restrict__ sinT,
                  __half* __restrict__ Qf, __half* __restrict__ Kf,
                  __half* __restrict__ Vf)
{
    extern __shared__ char gsm[];
    const int tid = threadIdx.x;
    GemmCtx g;
    g.sb = smem_u32(gsm);
    g.lane = tid & 31;
    const int wid = tid >> 5;
    g.warpM = wid & 1;          // 2 warps in M (64 rows each)
    g.warpN = wid >> 1;         // 4 warps in N (64 cols each)
    g.mBase = blockIdx.y * GBM;
    g.nBase = blockIdx.x * GBN;

    float acc[4][8][4];
    #pragma unroll
    for (int a = 0; a < 4; a++)
        #pragma unroll
        for (int b = 0; b < 8; b++)
            #pragma unroll
            for (int c2 = 0; c2 < 4; c2++) acc[a][b][c2] = 0.f;

    gemm_mainloop(g, Afg, Bg, DD, tid, acc);

    // ---- fused epilogue: RoPE (Q,K); all single fp16 ----
    // this warp's 64-col span is exactly one head-section column
    const int qrow = g.lane >> 2;
    const int qcol = (g.lane & 3) * 2;
    const float qscale = 0.125f * 1.4426950408889634f;  // HD^-0.5 * log2(e)

    const int colbase = g.nBase + g.warpN * 64;
    const int h3  = colbase >> 6;
    const int sec = h3 >> 4;                // 0=Q 1=K 2=V
    const int h   = h3 & 15;

    #pragma unroll
    for (int mt = 0; mt < 4; mt++) {
        const int r0 = g.mBase + g.warpM * 64 + mt * 16 + qrow;
        const int b  = r0 >> 11;          // /LL
        const int l0 = r0 & (LL - 1);
        const int l1 = l0 + 8;
        const size_t o0 = (((size_t)(b * HH + h) * LL) + l0) * HD;
        const size_t o1 = o0 + 8 * HD;
        #pragma unroll
        for (int n8 = 0; n8 < 4; n8++) {
            const int d = n8 * 8 + qcol;            // 0..31 within head

            const float a0 = acc[mt][n8][0], a1 = acc[mt][n8][1];
            const float a2 = acc[mt][n8][2], a3 = acc[mt][n8][3];
            const float b0 = acc[mt][n8 + 4][0], b1 = acc[mt][n8 + 4][1];
            const float b2 = acc[mt][n8 + 4][2], b3 = acc[mt][n8 + 4][3];

            if (sec == 2) {
                *(uint32_t*)(Vf + o0 + d)      = pack2h(a0, a1);
                *(uint32_t*)(Vf + o1 + d)      = pack2h(a2, a3);
                *(uint32_t*)(Vf + o0 + d + 32) = pack2h(b0, b1);
                *(uint32_t*)(Vf + o1 + d + 32) = pack2h(b2, b3);
            } else {
                const float2 cl0 = *(const float2*)(cosT + l0 * HD + d);
                const float2 ch0 = *(const float2*)(cosT + l0 * HD + d + 32);
                const float2 sl0 = *(const float2*)(sinT + l0 * HD + d);
                const float2 sh0 = *(const float2*)(sinT + l0 * HD + d + 32);
                const float2 cl1 = *(const float2*)(cosT + l1 * HD + d);
                const float2 ch1 = *(const float2*)(cosT + l1 * HD + d + 32);
                const float2 sl1 = *(const float2*)(sinT + l1 * HD + d);
                const float2 sh1 = *(const float2*)(sinT + l1 * HD + d + 32);

                // row l0
                float rl0 = a0 * cl0.x - b0 * sl0.x;
                float rl1 = a1 * cl0.y - b1 * sl0.y;
                float rh0 = b0 * ch0.x + a0 * sh0.x;
                float rh1 = b1 * ch0.y + a1 * sh0.y;
                // row l1
                float ql0 = a2 * cl1.x - b2 * sl1.x;
                float ql1 = a3 * cl1.y - b3 * sl1.y;
                float qh0 = b2 * ch1.x + a2 * sh1.x;
                float qh1 = b3 * ch1.y + a3 * sh1.y;

                if (sec == 0) {
                    *(uint32_t*)(Qf + o0 + d)      = pack2h(rl0 * qscale, rl1 * qscale);
                    *(uint32_t*)(Qf + o0 + d + 32) = pack2h(rh0 * qscale, rh1 * qscale);
                    *(uint32_t*)(Qf + o1 + d)      = pack2h(ql0 * qscale, ql1 * qscale);
                    *(uint32_t*)(Qf + o1 + d + 32) = pack2h(qh0 * qscale, qh1 * qscale);
                } else {
                    *(uint32_t*)(Kf + o0 + d)      = pack2h(rl0, rl1);
                    *(uint32_t*)(Kf + o0 + d + 32) = pack2h(rh0, rh1);
                    *(uint32_t*)(Kf + o1 + d)      = pack2h(ql0, ql1);
                    *(uint32_t*)(Kf + o1 + d + 32) = pack2h(qh0, qh1);
                }
            }
        }
    }
}

// ---- output projection GEMM (+bias), fp32 out ----------------------------
__global__ __launch_bounds__(256, 1)
void mma_gemm_bias(const __half* __restrict__ Afg, const __half* __restrict__ Bg,
                   const float* __restrict__ bias, float* __restrict__ C,
                   int Ntot, int K)
{
    extern __shared__ char gsm[];
    const int tid = threadIdx.x;
    GemmCtx g;
    g.sb = smem_u32(gsm);
    g.lane = tid & 31;
    const int wid = tid >> 5;
    g.warpM = wid & 1;
    g.warpN = wid >> 1;
    g.mBase = blockIdx.y * GBM;
    g.nBase = blockIdx.x * GBN;

    float acc[4][8][4];
    #pragma unroll
    for (int a = 0; a < 4; a++)
        #pragma unroll
        for (int b = 0; b < 8; b++)
            #pragma unroll
            for (int c2 = 0; c2 < 4; c2++) acc[a][b][c2] = 0.f;

    gemm_mainloop(g, Afg, Bg, K, tid, acc);

    const int qrow = g.lane >> 2;
    const int qcol = (g.lane & 3) * 2;
    #pragma unroll
    for (int mt = 0; mt < 4; mt++) {
        const int m0 = g.mBase + g.warpM * 64 + mt * 16 + qrow;
        #pragma unroll
        for (int n8 = 0; n8 < 8; n8++) {
            const int col = g.nBase + g.warpN * 64 + n8 * 8 + qcol;
            float2 v0, v1;
            v0.x = acc[mt][n8][0]; v0.y = acc[mt][n8][1];
            v1.x = acc[mt][n8][2]; v1.y = acc[mt][n8][3];
            const float b0 = bias[col], b1 = bias[col + 1];
            v0.x += b0; v0.y += b1;
            v1.x += b0; v1.y += b1;
            *(float2*)&C[(size_t)m0 * Ntot + col] = v0;
            *(float2*)&C[(size_t)(m0 + 8) * Ntot + col] = v1;
        }
    }
}

// --------------- flash attention (all single fp16, 3-stage KV ring) -------
#define RSTRIDE 144               // padded smem row (72 fp16)
#define ASQ  0                    // Q region: 128 * 144 = 18432
#define KVB  18432                // KV ring base (3 buffers)
#define KVSZ 18432                // one KV buffer (Kf, Vf @ 9216 each)
#define KOFF_V 9216
#define ATT_SMEM (KVB + 3 * KVSZ) // 73728

__global__ __launch_bounds__(256, 2)
void flash_attn(const __half* __restrict__ Qfg,
                const __half* __restrict__ Kfg, const __half* __restrict__ Vfg,
                __half* __restrict__ Of)
{
    extern __shared__ char smem[];
    const uint32_t sb = smem_u32(smem);
    const int tid = threadIdx.x, wid = tid >> 5, lane = tid & 31;
    const int qt = (LL / 128 - 1) - blockIdx.x;     // big tiles first
    const int bh = blockIdx.y;
    const int b = bh >> 4, h = bh & 15;
    const int q0 = qt * 128;
    const size_t base = (size_t)bh * LL * HD;

    const int ntiles = q0 / 64 + 2;

    auto stage_kv = [&](int t, int buf) {
        const int k0 = t * 64;
        const uint32_t bo = KVB + buf * KVSZ;
        #pragma unroll
        for (int j = 0; j < 2; j++) {
            const int item = j * 256 + tid;
            const int row = item >> 3, seg = item & 7;
            const size_t g = base + (size_t)(k0 + row) * HD + seg * 8;
            const uint32_t so = bo + row * RSTRIDE + seg * 16;
            cpa16(sb + so,           Kfg + g);
            cpa16(sb + so + KOFF_V,  Vfg + g);
        }
    };

    // ---- group 0: Q tile + KV tile 0; group 1: KV tile 1 ----
    {
        const int row = tid >> 1, seg = tid & 1;
        const size_t g = base + (size_t)(q0 + row) * HD + seg * 32;
        const uint32_t dq = sb + ASQ + row * RSTRIDE + seg * 64;
        #pragma unroll
        for (int i = 0; i < 4; i++)
            cpa16(dq + i * 16, Qfg + g + i * 8);
    }
    stage_kv(0, 0);
    CP_COMMIT();
    if (ntiles > 1) { stage_kv(1, 1); CP_COMMIT(); CP_WAIT1(); }
    else            { CP_WAIT0(); }
    __syncthreads();

    // ---- Q fragments (persistent; region never overwritten) ----
    uint32_t qf[4][4];
    {
        const uint32_t ro = (wid * 16 + (lane & 15)) * RSTRIDE + ((lane >> 4) << 4);
        #pragma unroll
        for (int ks = 0; ks < 4; ks++)
            ldsm4(qf[ks], sb + ASQ + ro + ks * 32);
    }

    float acc_o[8][4];
    #pragma unroll
    for (int j = 0; j < 8; j++)
        #pragma unroll
        for (int e = 0; e < 4; e++) acc_o[j][e] = 0.f;
    float m0 = -1e30f, m1 = -1e30f, l0 = 0.f, l1 = 0.f;

    const int qmin = q0 + wid * 16;
    const int r_lo = qmin + (lane >> 2);

    for (int t = 0; t < ntiles; t++) {
        const int k0 = t * 64;
        if (t > 0) {
            if (t + 1 < ntiles) { CP_WAIT1(); } else { CP_WAIT0(); }
            __syncthreads();
        }

        if (k0 <= qmin + 15) {                     // not fully masked for this warp
            const uint32_t kb = sb + KVB + (t % 3) * KVSZ;

            // ---- S = Q·Kᵀ (single term) ----
            float s[8][4];
            #pragma unroll
            for (int j = 0; j < 8; j++)
                #pragma unroll
                for (int e = 0; e < 4; e++) s[j][e] = 0.f;

            #pragma unroll
            for (int ks = 0; ks < 4; ks++) {
                #pragma unroll
                for (int kp = 0; kp < 2; kp++) {
                    uint32_t kf[2][4];
                    #pragma unroll
                    for (int i = 0; i < 2; i++) {
                        const int np = kp * 2 + i;
                        const uint32_t ro = (np * 16 + (lane & 15)) * RSTRIDE +
                                            ((lane >> 4) << 4) + ks * 32;
                        ldsm4(kf[i], kb + ro);
                    }
                    #pragma unroll
                    for (int i = 0; i < 2; i++) {
                        const int np = kp * 2 + i;
                        mma_f16(s[2 * np],     qf[ks], kf[i][0], kf[i][2]);
                        mma_f16(s[2 * np + 1], qf[ks], kf[i][1], kf[i][3]);
                    }
                }
            }

            // ---- causal mask ----
            if (k0 + 63 > qmin) {
                #pragma unroll
                for (int j = 0; j < 8; j++) {
                    const int key = k0 + j * 8 + (lane & 3) * 2;
                    if (key     > r_lo)     s[j][0] = -1e30f;
                    if (key + 1 > r_lo)     s[j][1] = -1e30f;
                    if (key     > r_lo + 8) s[j][2] = -1e30f;
                    if (key + 1 > r_lo + 8) s[j][3] = -1e30f;
                }
            }

            // ---- online softmax (log2 domain) ----
            float rm0 = -1e30f, rm1 = -1e30f;
            #pragma unroll
            for (int j = 0; j < 8; j++) {
                rm0 = fmaxf(rm0, fmaxf(s[j][0], s[j][1]));
                rm1 = fmaxf(rm1, fmaxf(s[j][2], s[j][3]));
            }
            rm0 = fmaxf(rm0, __shfl_xor_sync(0xffffffff, rm0, 1));
            rm0 = fmaxf(rm0, __shfl_xor_sync(0xffffffff, rm0, 2));
            rm1 = fmaxf(rm1, __shfl_xor_sync(0xffffffff, rm1, 1));
            rm1 = fmaxf(rm1, __shfl_xor_sync(0xffffffff, rm1, 2));

            const float mn0 = fmaxf(m0, rm0), mn1 = fmaxf(m1, rm1);
            const float c0 = fexp2(m0 - mn0), c1 = fexp2(m1 - mn1);
            m0 = mn0; m1 = mn1;
            l0 *= c0; l1 *= c1;
            #pragma unroll
            for (int j = 0; j < 8; j++) {
                acc_o[j][0] *= c0; acc_o[j][1] *= c0;
                acc_o[j][2] *= c1; acc_o[j][3] *= c1;
            }

            #pragma unroll
            for (int j = 0; j < 8; j++) {
                s[j][0] = fexp2(s[j][0] - m0);
                s[j][1] = fexp2(s[j][1] - m0);
                s[j][2] = fexp2(s[j][2] - m1);
                s[j][3] = fexp2(s[j][3] - m1);
                l0 += s[j][0] + s[j][1];
                l1 += s[j][2] + s[j][3];
            }

            // ---- O += P·V (P single fp16) ----
            #pragma unroll
            for (int ks = 0; ks < 4; ks++) {
                uint32_t pf[4];
                const int j0 = 2 * ks, j1 = 2 * ks + 1;
                pf[0] = pack2h(s[j0][0], s[j0][1]);
                pf[1] = pack2h(s[j0][2], s[j0][3]);
                pf[2] = pack2h(s[j1][0], s[j1][1]);
                pf[3] = pack2h(s[j1][2], s[j1][3]);

                #pragma unroll
                for (int vp = 0; vp < 2; vp++) {
                    uint32_t vf[2][4];
                    #pragma unroll
                    for (int i = 0; i < 2; i++) {
                        const int np = vp * 2 + i;
                        const int g = lane >> 3;
                        const uint32_t vrow = ks * 16 + (g & 1) * 8 + (lane & 7);
                        const uint32_t ro = vrow * RSTRIDE + np * 32 + (g >> 1) * 16;
                        ldsm4t(vf[i], kb + KOFF_V + ro);
                    }
                    #pragma unroll
                    for (int i = 0; i < 2; i++) {
                        const int np = vp * 2 + i;
                        mma_f16(acc_o[2 * np],     pf, vf[i][0], vf[i][1]);
                        mma_f16(acc_o[2 * np + 1], pf, vf[i][2], vf[i][3]);
                    }
                }
            }
        }

        if (t + 2 < ntiles) { stage_kv(t + 2, (t + 2) % 3); CP_COMMIT(); }
    }

    // ---- epilogue: normalize, write single fp16 [B*L, 1024] ----
    l0 += __shfl_xor_sync(0xffffffff, l0, 1);
    l0 += __shfl_xor_sync(0xffffffff, l0, 2);
    l1 += __shfl_xor_sync(0xffffffff, l1, 1);
    l1 += __shfl_xor_sync(0xffffffff, l1, 2);
    const float inv0 = 1.0f / l0, inv1 = 1.0f / l1;

    const size_t row0 = (size_t)(b * LL + q0 + wid * 16 + (lane >> 2));
    const size_t row1 = row0 + 8;
    const int colbase = h * HD + (lane & 3) * 2;
    #pragma unroll
    for (int j = 0; j < 8; j++) {
        const int col = colbase + j * 8;
        *(uint32_t*)(Of + row0 * DD + col) = pack2h(acc_o[j][0] * inv0, acc_o[j][1] * inv0);
        *(uint32_t*)(Of + row1 * DD + col) = pack2h(acc_o[j][2] * inv1, acc_o[j][3] * inv1);
    }
}

// -------------------------------------------------------------------------
extern "C" void kernel_launch(void* const* d_in, const int* in_sizes, int n_in,
                              void* d_out, int out_size)
{
    const float* x        = (const float*)d_in[0];
    const float* rope_cos = (const float*)d_in[1];
    const float* rope_sin = (const float*)d_in[2];
    const float* W_qkv    = (const float*)d_in[3];
    const float* W_out    = (const float*)d_in[4];
    const float* b_out    = (const float*)d_in[5];
    float* out = (float*)d_out;

    __half *xf, *wq, *wo, *attf, *Qf, *Kf, *Vf;
    cudaGetSymbolAddress((void**)&xf,   g_xf);
    cudaGetSymbolAddress((void**)&wq,   g_wqkvT);
    cudaGetSymbolAddress((void**)&wo,   g_woutT);
    cudaGetSymbolAddress((void**)&attf, g_attf);
    cudaGetSymbolAddress((void**)&Qf,   g_Qf);
    cudaGetSymbolAddress((void**)&Kf,   g_Kf);
    cudaGetSymbolAddress((void**)&Vf,   g_Vf);

    cudaFuncSetAttribute(flash_attn,    cudaFuncAttributeMaxDynamicSharedMemorySize, ATT_SMEM);
    cudaFuncSetAttribute(mma_gemm_qkv,  cudaFuncAttributeMaxDynamicSharedMemorySize, GEMM_SMEM);
    cudaFuncSetAttribute(mma_gemm_bias, cudaFuncAttributeMaxDynamicSharedMemorySize, GEMM_SMEM);

    // 0) operand conversion (all single fp16)
    conv_half<<<(MROWS * DD / 4 + 255) / 256, 256>>>(x, xf, MROWS * DD / 4);
    conv_halfT<<<dim3(NQKV / 32, DD / 32), dim3(32, 8)>>>(W_qkv, wq, DD, NQKV);
    conv_halfT<<<dim3(DD / 32, DD / 32),   dim3(32, 8)>>>(W_out, wo, DD, DD);

    // 1) QKV projection + fused RoPE epilogue -> Qf, Kf, Vf [B,H,L,HD]
    mma_gemm_qkv<<<dim3(NQKV / GBN, MROWS / GBM), 256, GEMM_SMEM>>>(
        xf, wq, rope_cos, rope_sin, Qf, Kf, Vf);

    // 2) flash attention (all single fp16) -> attf
    flash_attn<<<dim3(LL / 128, BB * HH), 256, ATT_SMEM>>>(
        Qf, Kf, Vf, attf);

    // 3) output projection + bias
    mma_gemm_bias<<<dim3(DD / GBN, MROWS / GBM), 256, GEMM_SMEM>>>(
        attf, wo, b_out, out, DD, DD);
}

// round 13
// speedup vs baseline: 1.0037x; 1.0037x over previous
#include <cuda_runtime.h>
#include <cuda_fp16.h>
#include <cstdint>

// Problem constants
#define BB 2
#define LL 2048
#define DD 1024
#define HH 16
#define HD 64
#define NQKV 3072        // 3*H*HD
#define MROWS (BB*LL)    // 4096

// ---------------- scratch (device globals; no allocations allowed) -------
__device__ __half g_xf[MROWS * DD];               // x single fp16
__device__ __half g_wqkvT[NQKV * DD];             // [N][K] single
__device__ __half g_woutT[DD * DD];               // [N][K] single

// attention operands, fp16 single, [B,H,L,HD] (Q scaled by 0.125*log2e)
__device__ __half g_Qf[BB * HH * LL * HD];
__device__ __half g_Kf[BB * HH * LL * HD];
__device__ __half g_Vf[BB * HH * LL * HD];
__device__ __half g_attf[MROWS * DD];             // [B*L, 1024] single

// ==================== helpers =============================================
__device__ __forceinline__ uint32_t smem_u32(const void* p) {
    uint32_t a;
    asm("{ .reg .u64 t; cvta.to.shared.u64 t, %1; cvt.u32.u64 %0, t; }"
        : "=r"(a) : "l"(p));
    return a;
}

// pack two floats -> half2 reg (a in low half)
__device__ __forceinline__ uint32_t pack2h(float a, float b) {
    __half2 h = __floats2half2_rn(a, b);
    return *(uint32_t*)&h;
}

__device__ __forceinline__ void ldsm4(uint32_t* r, uint32_t addr) {
    asm volatile("ldmatrix.sync.aligned.m8n8.x4.shared.b16 {%0,%1,%2,%3}, [%4];"
                 : "=r"(r[0]), "=r"(r[1]), "=r"(r[2]), "=r"(r[3]) : "r"(addr));
}

__device__ __forceinline__ void ldsm4t(uint32_t* r, uint32_t addr) {
    asm volatile("ldmatrix.sync.aligned.m8n8.x4.trans.shared.b16 {%0,%1,%2,%3}, [%4];"
                 : "=r"(r[0]), "=r"(r[1]), "=r"(r[2]), "=r"(r[3]) : "r"(addr));
}

__device__ __forceinline__ void mma_f16(float* d, const uint32_t* a, uint32_t b0, uint32_t b1) {
    asm volatile(
        "mma.sync.aligned.m16n8k16.row.col.f32.f16.f16.f32 "
        "{%0,%1,%2,%3}, {%4,%5,%6,%7}, {%8,%9}, {%0,%1,%2,%3};"
        : "+f"(d[0]), "+f"(d[1]), "+f"(d[2]), "+f"(d[3])
        : "r"(a[0]), "r"(a[1]), "r"(a[2]), "r"(a[3]), "r"(b0), "r"(b1));
}

// cp.async with L1 caching (.ca)
__device__ __forceinline__ void cpa16(uint32_t dst, const void* src) {
    asm volatile("cp.async.ca.shared.global [%0], [%1], 16;" :: "r"(dst), "l"(src));
}
#define CP_COMMIT() asm volatile("cp.async.commit_group;" ::: "memory")
#define CP_WAIT0()  asm volatile("cp.async.wait_group 0;" ::: "memory")
#define CP_WAIT1()  asm volatile("cp.async.wait_group 1;" ::: "memory")

// fast exp2 on FMA pipe (x <= 0 expected; clamped at -120)
__device__ __forceinline__ float fexp2(float x) {
    x = fmaxf(x, -120.0f);
    float n = floorf(x);
    float f = x - n;
    float p = 1.5404226e-4f;
    p = fmaf(p, f, 1.3333558e-3f);
    p = fmaf(p, f, 9.6181291e-3f);
    p = fmaf(p, f, 5.5504109e-2f);
    p = fmaf(p, f, 2.4022651e-1f);
    p = fmaf(p, f, 6.9314718e-1f);
    p = fmaf(p, f, 1.0f);
    return __int_as_float(__float_as_int(p) + (((int)n) << 23));
}

// ==================== conversion kernels ==================================
__global__ void conv_half(const float* __restrict__ src,
                          __half* __restrict__ dst, int n4)
{
    const int i = blockIdx.x * blockDim.x + threadIdx.x;
    if (i >= n4) return;
    float4 v = ((const float4*)src)[i];
    __half h[4];
    h[0] = __float2half_rn(v.x);
    h[1] = __float2half_rn(v.y);
    h[2] = __float2half_rn(v.z);
    h[3] = __float2half_rn(v.w);
    ((uint2*)dst)[i] = *(uint2*)h;
}

// W[K][N] fp32 -> T [N][K] single fp16 (transpose)
__global__ void conv_halfT(const float* __restrict__ W,
                           __half* __restrict__ T,
                           int Kdim, int Ndim)
{
    __shared__ float t[32][33];
    const int tx = threadIdx.x, ty = threadIdx.y;
    const int nb = blockIdx.x * 32;
    const int kb = blockIdx.y * 32;
    #pragma unroll
    for (int i = 0; i < 4; i++)
        t[ty + i * 8][tx] = W[(size_t)(kb + ty + i * 8) * Ndim + nb + tx];
    __syncthreads();
    #pragma unroll
    for (int i = 0; i < 4; i++) {
        const float v = t[tx][ty + i * 8];
        T[(size_t)(nb + ty + i * 8) * Kdim + kb + tx] = __float2half_rn(v);
    }
}

// ====== GEMM: CTA 128x128, warp 32x64, K-chunk 64, 3-stage ring ==========
#define GBM 128
#define GBN 128
#define GBK 64
#define SROW 36                       // padded row stride (u32) = 144B
#define GOP  (GBM * SROW * 4)         // one operand buffer: 18432 B
#define GA   0                        // A (3 buffers)
#define GB   (3 * GOP)                // W (3 buffers)
#define GEMM_SMEM (6 * GOP)           // 110592 B

struct GemmCtx {
    uint32_t sb;
    int warpM, warpN, lane;
    int mBase, nBase;
};

__device__ __forceinline__ void gemm_mainloop(
    const GemmCtx& g, const __half* Afg, const __half* Bg,
    int K, int tid, float acc[2][8][4])
{
    const int row = tid >> 1;
    const int seg = tid & 1;                 // 64B half of the 128B row
    const uint32_t so = row * (SROW * 4) + seg * 64;
    const int nchunks = K / GBK;
    const uint32_t lrow = g.lane & 15;
    const uint32_t lhi  = (g.lane >> 4) << 4;

    auto stage = [&](int c, int buf) {
        const int k0 = c * GBK;
        const size_t ga = (size_t)(g.mBase + row) * K + k0 + seg * 32;
        const size_t gb = (size_t)(g.nBase + row) * K + k0 + seg * 32;
        const uint32_t da = g.sb + GA + buf * GOP + so;
        const uint32_t db = g.sb + GB + buf * GOP + so;
        cpa16(da,      Afg + ga);
        cpa16(da + 16, Afg + ga + 8);
        cpa16(da + 32, Afg + ga + 16);
        cpa16(da + 48, Afg + ga + 24);
        cpa16(db,      Bg + gb);
        cpa16(db + 16, Bg + gb + 8);
        cpa16(db + 32, Bg + gb + 16);
        cpa16(db + 48, Bg + gb + 24);
    };

    stage(0, 0); CP_COMMIT();
    stage(1, 1); CP_COMMIT();

    for (int c = 0; c < nchunks; c++) {
        if (c + 1 < nchunks) { CP_WAIT1(); } else { CP_WAIT0(); }
        __syncthreads();

        const uint32_t bA = g.sb + GA + (c % 3) * GOP;
        const uint32_t bB = g.sb + GB + (c % 3) * GOP;

        #pragma unroll
        for (int ks = 0; ks < 4; ks++) {
            const uint32_t kboff = ks * 32 + lhi;
            uint32_t ah[2][4];
            uint32_t bf[4][4];
            #pragma unroll
            for (int mt = 0; mt < 2; mt++) {
                const uint32_t ro = (g.warpM * 32 + mt * 16 + lrow) * (SROW * 4) + kboff;
                ldsm4(ah[mt], bA + ro);
            }
            #pragma unroll
            for (int reg = 0; reg < 4; reg++) {
                const uint32_t ro = (g.warpN * 64 + reg * 16 + lrow) * (SROW * 4) + kboff;
                ldsm4(bf[reg], bB + ro);
            }
            #pragma unroll
            for (int reg = 0; reg < 4; reg++)
                #pragma unroll
                for (int mt = 0; mt < 2; mt++)
                    #pragma unroll
                    for (int t = 0; t < 2; t++)
                        mma_f16(acc[mt][reg * 2 + t], ah[mt], bf[reg][t], bf[reg][t + 2]);
        }

        if (c + 2 < nchunks) { stage(c + 2, (c + 2) % 3); CP_COMMIT(); }
    }
}

// ---- QKV GEMM with fused RoPE epilogue: Q/K/V single fp16 ---------------
__global__ __launch_bounds__(256, 2)
void mma_gemm_qkv(const __half* __restrict__ Afg, const __half* __restrict__ Bg,
                  const float* __restrict__ cosT, const float* __restrict__ sinT,
                  __half* __restrict__ Qf, __half* __restrict__ Kf,
                  __half* __restrict__ Vf)
{
    extern __shared__ char gsm[];
    const int tid = threadIdx.x;
    GemmCtx g;
    g.sb = smem_u32(gsm);
    g.lane = tid & 31;
    const int wid = tid >> 5;
    g.warpM = wid & 3;          // 4 warps in M (32 rows each)
    g.warpN = wid >> 2;         // 2 warps in N (64 cols each)
    g.mBase = blockIdx.y * GBM;
    g.nBase = blockIdx.x * GBN;

    float acc[2][8][4];
    #pragma unroll
    for (int a = 0; a < 2; a++)
        #pragma unroll
        for (int b = 0; b < 8; b++)
            #pragma unroll
            for (int c2 = 0; c2 < 4; c2++) acc[a][b][c2] = 0.f;

    gemm_mainloop(g, Afg, Bg, DD, tid, acc);

    // ---- fused epilogue: RoPE (Q,K); all single fp16 ----
    // warp's 64-col span is exactly one head-section column
    const int qrow = g.lane >> 2;
    const int qcol = (g.lane & 3) * 2;
    const float qscale = 0.125f * 1.4426950408889634f;  // HD^-0.5 * log2(e)

    const int colbase = g.nBase + g.warpN * 64;
    const int h3  = colbase >> 6;
    const int sec = h3 >> 4;                // 0=Q 1=K 2=V
    const int h   = h3 & 15;

    #pragma unroll
    for (int mt = 0; mt < 2; mt++) {
        const int r0 = g.mBase + g.warpM * 32 + mt * 16 + qrow;
        const int b  = r0 >> 11;          // /LL
        const int l0 = r0 & (LL - 1);
        const int l1 = l0 + 8;
        const size_t o0 = (((size_t)(b * HH + h) * LL) + l0) * HD;
        const size_t o1 = o0 + 8 * HD;
        #pragma unroll
        for (int n8 = 0; n8 < 4; n8++) {
            const int d = n8 * 8 + qcol;            // 0..31 within head

            const float a0 = acc[mt][n8][0], a1 = acc[mt][n8][1];
            const float a2 = acc[mt][n8][2], a3 = acc[mt][n8][3];
            const float b0 = acc[mt][n8 + 4][0], b1 = acc[mt][n8 + 4][1];
            const float b2 = acc[mt][n8 + 4][2], b3 = acc[mt][n8 + 4][3];

            if (sec == 2) {
                *(uint32_t*)(Vf + o0 + d)      = pack2h(a0, a1);
                *(uint32_t*)(Vf + o1 + d)      = pack2h(a2, a3);
                *(uint32_t*)(Vf + o0 + d + 32) = pack2h(b0, b1);
                *(uint32_t*)(Vf + o1 + d + 32) = pack2h(b2, b3);
            } else {
                const float2 cl0 = *(const float2*)(cosT + l0 * HD + d);
                const float2 ch0 = *(const float2*)(cosT + l0 * HD + d + 32);
                const float2 sl0 = *(const float2*)(sinT + l0 * HD + d);
                const float2 sh0 = *(const float2*)(sinT + l0 * HD + d + 32);
                const float2 cl1 = *(const float2*)(cosT + l1 * HD + d);
                const float2 ch1 = *(const float2*)(cosT + l1 * HD + d + 32);
                const float2 sl1 = *(const float2*)(sinT + l1 * HD + d);
                const float2 sh1 = *(const float2*)(sinT + l1 * HD + d + 32);

                // row l0
                float rl0 = a0 * cl0.x - b0 * sl0.x;
                float rl1 = a1 * cl0.y - b1 * sl0.y;
                float rh0 = b0 * ch0.x + a0 * sh0.x;
                float rh1 = b1 * ch0.y + a1 * sh0.y;
                // row l1
                float ql0 = a2 * cl1.x - b2 * sl1.x;
                float ql1 = a3 * cl1.y - b3 * sl1.y;
                float qh0 = b2 * ch1.x + a2 * sh1.x;
                float qh1 = b3 * ch1.y + a3 * sh1.y;

                if (sec == 0) {
                    *(uint32_t*)(Qf + o0 + d)      = pack2h(rl0 * qscale, rl1 * qscale);
                    *(uint32_t*)(Qf + o0 + d + 32) = pack2h(rh0 * qscale, rh1 * qscale);
                    *(uint32_t*)(Qf + o1 + d)      = pack2h(ql0 * qscale, ql1 * qscale);
                    *(uint32_t*)(Qf + o1 + d + 32) = pack2h(qh0 * qscale, qh1 * qscale);
                } else {
                    *(uint32_t*)(Kf + o0 + d)      = pack2h(rl0, rl1);
                    *(uint32_t*)(Kf + o0 + d + 32) = pack2h(rh0, rh1);
                    *(uint32_t*)(Kf + o1 + d)      = pack2h(ql0, ql1);
                    *(uint32_t*)(Kf + o1 + d + 32) = pack2h(qh0, qh1);
                }
            }
        }
    }
}

// ---- output projection GEMM (+bias), fp32 out ----------------------------
__global__ __launch_bounds__(256, 2)
void mma_gemm_bias(const __half* __restrict__ Afg, const __half* __restrict__ Bg,
                   const float* __restrict__ bias, float* __restrict__ C,
                   int Ntot, int K)
{
    extern __shared__ char gsm[];
    const int tid = threadIdx.x;
    GemmCtx g;
    g.sb = smem_u32(gsm);
    g.lane = tid & 31;
    const int wid = tid >> 5;
    g.warpM = wid & 3;
    g.warpN = wid >> 2;
    g.mBase = blockIdx.y * GBM;
    g.nBase = blockIdx.x * GBN;

    float acc[2][8][4];
    #pragma unroll
    for (int a = 0; a < 2; a++)
        #pragma unroll
        for (int b = 0; b < 8; b++)
            #pragma unroll
            for (int c2 = 0; c2 < 4; c2++) acc[a][b][c2] = 0.f;

    gemm_mainloop(g, Afg, Bg, K, tid, acc);

    const int qrow = g.lane >> 2;
    const int qcol = (g.lane & 3) * 2;
    #pragma unroll
    for (int mt = 0; mt < 2; mt++) {
        const int m0 = g.mBase + g.warpM * 32 + mt * 16 + qrow;
        #pragma unroll
        for (int n8 = 0; n8 < 8; n8++) {
            const int col = g.nBase + g.warpN * 64 + n8 * 8 + qcol;
            float2 v0, v1;
            v0.x = acc[mt][n8][0]; v0.y = acc[mt][n8][1];
            v1.x = acc[mt][n8][2]; v1.y = acc[mt][n8][3];
            const float b0 = bias[col], b1 = bias[col + 1];
            v0.x += b0; v0.y += b1;
            v1.x += b0; v1.y += b1;
            *(float2*)&C[(size_t)m0 * Ntot + col] = v0;
            *(float2*)&C[(size_t)(m0 + 8) * Ntot + col] = v1;
        }
    }
}

// --------------- flash attention (all single fp16, 3-stage KV ring) -------
#define RSTRIDE 144               // padded smem row (72 fp16)
#define ASQ  0                    // Q region: 128 * 144 = 18432
#define KVB  18432                // KV ring base (3 buffers)
#define KVSZ 18432                // one KV buffer (Kf, Vf @ 9216 each)
#define KOFF_V 9216
#define ATT_SMEM (KVB + 3 * KVSZ) // 73728

__global__ __launch_bounds__(256, 2)
void flash_attn(const __half* __restrict__ Qfg,
                const __half* __restrict__ Kfg, const __half* __restrict__ Vfg,
                __half* __restrict__ Of)
{
    extern __shared__ char smem[];
    const uint32_t sb = smem_u32(smem);
    const int tid = threadIdx.x, wid = tid >> 5, lane = tid & 31;
    const int qt = (LL / 128 - 1) - blockIdx.x;     // big tiles first
    const int bh = blockIdx.y;
    const int b = bh >> 4, h = bh & 15;
    const int q0 = qt * 128;
    const size_t base = (size_t)bh * LL * HD;

    const int ntiles = q0 / 64 + 2;

    auto stage_kv = [&](int t, int buf) {
        const int k0 = t * 64;
        const uint32_t bo = KVB + buf * KVSZ;
        #pragma unroll
        for (int j = 0; j < 2; j++) {
            const int item = j * 256 + tid;
            const int row = item >> 3, seg = item & 7;
            const size_t g = base + (size_t)(k0 + row) * HD + seg * 8;
            const uint32_t so = bo + row * RSTRIDE + seg * 16;
            cpa16(sb + so,           Kfg + g);
            cpa16(sb + so + KOFF_V,  Vfg + g);
        }
    };

    // ---- group 0: Q tile + KV tile 0; group 1: KV tile 1 ----
    {
        const int row = tid >> 1, seg = tid & 1;
        const size_t g = base + (size_t)(q0 + row) * HD + seg * 32;
        const uint32_t dq = sb + ASQ + row * RSTRIDE + seg * 64;
        #pragma unroll
        for (int i = 0; i < 4; i++)
            cpa16(dq + i * 16, Qfg + g + i * 8);
    }
    stage_kv(0, 0);
    CP_COMMIT();
    if (ntiles > 1) { stage_kv(1, 1); CP_COMMIT(); CP_WAIT1(); }
    else            { CP_WAIT0(); }
    __syncthreads();

    // ---- Q fragments (persistent; region never overwritten) ----
    uint32_t qf[4][4];
    {
        const uint32_t ro = (wid * 16 + (lane & 15)) * RSTRIDE + ((lane >> 4) << 4);
        #pragma unroll
        for (int ks = 0; ks < 4; ks++)
            ldsm4(qf[ks], sb + ASQ + ro + ks * 32);
    }

    float acc_o[8][4];
    #pragma unroll
    for (int j = 0; j < 8; j++)
        #pragma unroll
        for (int e = 0; e < 4; e++) acc_o[j][e] = 0.f;
    float m0 = -1e30f, m1 = -1e30f, l0 = 0.f, l1 = 0.f;

    const int qmin = q0 + wid * 16;
    const int r_lo = qmin + (lane >> 2);

    for (int t = 0; t < ntiles; t++) {
        const int k0 = t * 64;
        if (t > 0) {
            if (t + 1 < ntiles) { CP_WAIT1(); } else { CP_WAIT0(); }
            __syncthreads();
        }

        if (k0 <= qmin + 15) {                     // not fully masked for this warp
            const uint32_t kb = sb + KVB + (t % 3) * KVSZ;

            // ---- S = Q·Kᵀ (single term) ----
            float s[8][4];
            #pragma unroll
            for (int j = 0; j < 8; j++)
                #pragma unroll
                for (int e = 0; e < 4; e++) s[j][e] = 0.f;

            #pragma unroll
            for (int ks = 0; ks < 4; ks++) {
                #pragma unroll
                for (int kp = 0; kp < 2; kp++) {
                    uint32_t kf[2][4];
                    #pragma unroll
                    for (int i = 0; i < 2; i++) {
                        const int np = kp * 2 + i;
                        const uint32_t ro = (np * 16 + (lane & 15)) * RSTRIDE +
                                            ((lane >> 4) << 4) + ks * 32;
                        ldsm4(kf[i], kb + ro);
                    }
                    #pragma unroll
                    for (int i = 0; i < 2; i++) {
                        const int np = kp * 2 + i;
                        mma_f16(s[2 * np],     qf[ks], kf[i][0], kf[i][2]);
                        mma_f16(s[2 * np + 1], qf[ks], kf[i][1], kf[i][3]);
                    }
                }
            }

            // ---- causal mask ----
            if (k0 + 63 > qmin) {
                #pragma unroll
                for (int j = 0; j < 8; j++) {
                    const int key = k0 + j * 8 + (lane & 3) * 2;
                    if (key     > r_lo)     s[j][0] = -1e30f;
                    if (key + 1 > r_lo)     s[j][1] = -1e30f;
                    if (key     > r_lo + 8) s[j][2] = -1e30f;
                    if (key + 1 > r_lo + 8) s[j][3] = -1e30f;
                }
            }

            // ---- online softmax (log2 domain) ----
            float rm0 = -1e30f, rm1 = -1e30f;
            #pragma unroll
            for (int j = 0; j < 8; j++) {
                rm0 = fmaxf(rm0, fmaxf(s[j][0], s[j][1]));
                rm1 = fmaxf(rm1, fmaxf(s[j][2], s[j][3]));
            }
            rm0 = fmaxf(rm0, __shfl_xor_sync(0xffffffff, rm0, 1));
            rm0 = fmaxf(rm0, __shfl_xor_sync(0xffffffff, rm0, 2));
            rm1 = fmaxf(rm1, __shfl_xor_sync(0xffffffff, rm1, 1));
            rm1 = fmaxf(rm1, __shfl_xor_sync(0xffffffff, rm1, 2));

            const float mn0 = fmaxf(m0, rm0), mn1 = fmaxf(m1, rm1);
            const float c0 = fexp2(m0 - mn0), c1 = fexp2(m1 - mn1);
            m0 = mn0; m1 = mn1;
            l0 *= c0; l1 *= c1;
            #pragma unroll
            for (int j = 0; j < 8; j++) {
                acc_o[j][0] *= c0; acc_o[j][1] *= c0;
                acc_o[j][2] *= c1; acc_o[j][3] *= c1;
            }

            #pragma unroll
            for (int j = 0; j < 8; j++) {
                s[j][0] = fexp2(s[j][0] - m0);
                s[j][1] = fexp2(s[j][1] - m0);
                s[j][2] = fexp2(s[j][2] - m1);
                s[j][3] = fexp2(s[j][3] - m1);
                l0 += s[j][0] + s[j][1];
                l1 += s[j][2] + s[j][3];
            }

            // ---- O += P·V (P single fp16) ----
            #pragma unroll
            for (int ks = 0; ks < 4; ks++) {
                uint32_t pf[4];
                const int j0 = 2 * ks, j1 = 2 * ks + 1;
                pf[0] = pack2h(s[j0][0], s[j0][1]);
                pf[1] = pack2h(s[j0][2], s[j0][3]);
                pf[2] = pack2h(s[j1][0], s[j1][1]);
                pf[3] = pack2h(s[j1][2], s[j1][3]);

                #pragma unroll
                for (int vp = 0; vp < 2; vp++) {
                    uint32_t vf[2][4];
                    #pragma unroll
                    for (int i = 0; i < 2; i++) {
                        const int np = vp * 2 + i;
                        const int g = lane >> 3;
                        const uint32_t vrow = ks * 16 + (g & 1) * 8 + (lane & 7);
                        const uint32_t ro = vrow * RSTRIDE + np * 32 + (g >> 1) * 16;
                        ldsm4t(vf[i], kb + KOFF_V + ro);
                    }
                    #pragma unroll
                    for (int i = 0; i < 2; i++) {
                        const int np = vp * 2 + i;
                        mma_f16(acc_o[2 * np],     pf, vf[i][0], vf[i][1]);
                        mma_f16(acc_o[2 * np + 1], pf, vf[i][2], vf[i][3]);
                    }
                }
            }
        }

        if (t + 2 < ntiles) { stage_kv(t + 2, (t + 2) % 3); CP_COMMIT(); }
    }

    // ---- epilogue: normalize, write single fp16 [B*L, 1024] ----
    l0 += __shfl_xor_sync(0xffffffff, l0, 1);
    l0 += __shfl_xor_sync(0xffffffff, l0, 2);
    l1 += __shfl_xor_sync(0xffffffff, l1, 1);
    l1 += __shfl_xor_sync(0xffffffff, l1, 2);
    const float inv0 = 1.0f / l0, inv1 = 1.0f / l1;

    const size_t row0 = (size_t)(b * LL + q0 + wid * 16 + (lane >> 2));
    const size_t row1 = row0 + 8;
    const int colbase = h * HD + (lane & 3) * 2;
    #pragma unroll
    for (int j = 0; j < 8; j++) {
        const int col = colbase + j * 8;
        *(uint32_t*)(Of + row0 * DD + col) = pack2h(acc_o[j][0] * inv0, acc_o[j][1] * inv0);
        *(uint32_t*)(Of + row1 * DD + col) = pack2h(acc_o[j][2] * inv1, acc_o[j][3] * inv1);
    }
}

// -------------------------------------------------------------------------
extern "C" void kernel_launch(void* const* d_in, const int* in_sizes, int n_in,
                              void* d_out, int out_size)
{
    const float* x        = (const float*)d_in[0];
    const float* rope_cos = (const float*)d_in[1];
    const float* rope_sin = (const float*)d_in[2];
    const float* W_qkv    = (const float*)d_in[3];
    const float* W_out    = (const float*)d_in[4];
    const float* b_out    = (const float*)d_in[5];
    float* out = (float*)d_out;

    __half *xf, *wq, *wo, *attf, *Qf, *Kf, *Vf;
    cudaGetSymbolAddress((void**)&xf,   g_xf);
    cudaGetSymbolAddress((void**)&wq,   g_wqkvT);
    cudaGetSymbolAddress((void**)&wo,   g_woutT);
    cudaGetSymbolAddress((void**)&attf, g_attf);
    cudaGetSymbolAddress((void**)&Qf,   g_Qf);
    cudaGetSymbolAddress((void**)&Kf,   g_Kf);
    cudaGetSymbolAddress((void**)&Vf,   g_Vf);

    cudaFuncSetAttribute(flash_attn,    cudaFuncAttributeMaxDynamicSharedMemorySize, ATT_SMEM);
    cudaFuncSetAttribute(mma_gemm_qkv,  cudaFuncAttributeMaxDynamicSharedMemorySize, GEMM_SMEM);
    cudaFuncSetAttribute(mma_gemm_bias, cudaFuncAttributeMaxDynamicSharedMemorySize, GEMM_SMEM);

    // 0) operand conversion (all single fp16)
    conv_half<<<(MROWS * DD / 4 + 255) / 256, 256>>>(x, xf, MROWS * DD / 4);
    conv_halfT<<<dim3(NQKV / 32, DD / 32), dim3(32, 8)>>>(W_qkv, wq, DD, NQKV);
    conv_halfT<<<dim3(DD / 32, DD / 32),   dim3(32, 8)>>>(W_out, wo, DD, DD);

    // 1) QKV projection + fused RoPE epilogue -> Qf, Kf, Vf [B,H,L,HD]
    mma_gemm_qkv<<<dim3(NQKV / GBN, MROWS / GBM), 256, GEMM_SMEM>>>(
        xf, wq, rope_cos, rope_sin, Qf, Kf, Vf);

    // 2) flash attention (all single fp16) -> attf
    flash_attn<<<dim3(LL / 128, BB * HH), 256, ATT_SMEM>>>(
        Qf, Kf, Vf, attf);

    // 3) output projection + bias
    mma_gemm_bias<<<dim3(DD / GBN, MROWS / GBM), 256, GEMM_SMEM>>>(
        attf, wo, b_out, out, DD, DD);
}

// round 14
// speedup vs baseline: 1.0249x; 1.0211x over previous
#include <cuda_runtime.h>
#include <cuda_fp16.h>
#include <cstdint>

// Problem constants
#define BB 2
#define LL 2048
#define DD 1024
#define HH 16
#define HD 64
#define NQKV 3072        // 3*H*HD
#define MROWS (BB*LL)    // 4096

// ---------------- scratch (device globals; no allocations allowed) -------
__device__ __half g_xf[MROWS * DD];               // x single fp16
__device__ __half g_wqkvT[NQKV * DD];             // [N][K] single
__device__ __half g_woutT[DD * DD];               // [N][K] single

// attention operands, fp16 single, [B,H,L,HD] (Q scaled by 0.125*log2e)
__device__ __half g_Qf[BB * HH * LL * HD];
__device__ __half g_Kf[BB * HH * LL * HD];
__device__ __half g_Vf[BB * HH * LL * HD];
__device__ __half g_attf[MROWS * DD];             // [B*L, 1024] single

// ==================== helpers =============================================
__device__ __forceinline__ uint32_t smem_u32(const void* p) {
    uint32_t a;
    asm("{ .reg .u64 t; cvta.to.shared.u64 t, %1; cvt.u32.u64 %0, t; }"
        : "=r"(a) : "l"(p));
    return a;
}

// pack two floats -> half2 reg (a in low half)
__device__ __forceinline__ uint32_t pack2h(float a, float b) {
    __half2 h = __floats2half2_rn(a, b);
    return *(uint32_t*)&h;
}

__device__ __forceinline__ void ldsm4(uint32_t* r, uint32_t addr) {
    asm volatile("ldmatrix.sync.aligned.m8n8.x4.shared.b16 {%0,%1,%2,%3}, [%4];"
                 : "=r"(r[0]), "=r"(r[1]), "=r"(r[2]), "=r"(r[3]) : "r"(addr));
}

__device__ __forceinline__ void ldsm4t(uint32_t* r, uint32_t addr) {
    asm volatile("ldmatrix.sync.aligned.m8n8.x4.trans.shared.b16 {%0,%1,%2,%3}, [%4];"
                 : "=r"(r[0]), "=r"(r[1]), "=r"(r[2]), "=r"(r[3]) : "r"(addr));
}

__device__ __forceinline__ void mma_f16(float* d, const uint32_t* a, uint32_t b0, uint32_t b1) {
    asm volatile(
        "mma.sync.aligned.m16n8k16.row.col.f32.f16.f16.f32 "
        "{%0,%1,%2,%3}, {%4,%5,%6,%7}, {%8,%9}, {%0,%1,%2,%3};"
        : "+f"(d[0]), "+f"(d[1]), "+f"(d[2]), "+f"(d[3])
        : "r"(a[0]), "r"(a[1]), "r"(a[2]), "r"(a[3]), "r"(b0), "r"(b1));
}

// cp.async with L1 caching (.ca)
__device__ __forceinline__ void cpa16(uint32_t dst, const void* src) {
    asm volatile("cp.async.ca.shared.global [%0], [%1], 16;" :: "r"(dst), "l"(src));
}
#define CP_COMMIT() asm volatile("cp.async.commit_group;" ::: "memory")
#define CP_WAIT0()  asm volatile("cp.async.wait_group 0;" ::: "memory")
#define CP_WAIT1()  asm volatile("cp.async.wait_group 1;" ::: "memory")

// fast exp2 on FMA pipe (x <= 0 expected; clamped at -120)
__device__ __forceinline__ float fexp2(float x) {
    x = fmaxf(x, -120.0f);
    float n = floorf(x);
    float f = x - n;
    float p = 1.5404226e-4f;
    p = fmaf(p, f, 1.3333558e-3f);
    p = fmaf(p, f, 9.6181291e-3f);
    p = fmaf(p, f, 5.5504109e-2f);
    p = fmaf(p, f, 2.4022651e-1f);
    p = fmaf(p, f, 6.9314718e-1f);
    p = fmaf(p, f, 1.0f);
    return __int_as_float(__float_as_int(p) + (((int)n) << 23));
}

// ==================== conversion kernels ==================================
__global__ void conv_half(const float* __restrict__ src,
                          __half* __restrict__ dst, int n4)
{
    const int i = blockIdx.x * blockDim.x + threadIdx.x;
    if (i >= n4) return;
    float4 v = ((const float4*)src)[i];
    __half h[4];
    h[0] = __float2half_rn(v.x);
    h[1] = __float2half_rn(v.y);
    h[2] = __float2half_rn(v.z);
    h[3] = __float2half_rn(v.w);
    ((uint2*)dst)[i] = *(uint2*)h;
}

// W[K][N] fp32 -> T [N][K] single fp16 (transpose)
__global__ void conv_halfT(const float* __restrict__ W,
                           __half* __restrict__ T,
                           int Kdim, int Ndim)
{
    __shared__ float t[32][33];
    const int tx = threadIdx.x, ty = threadIdx.y;
    const int nb = blockIdx.x * 32;
    const int kb = blockIdx.y * 32;
    #pragma unroll
    for (int i = 0; i < 4; i++)
        t[ty + i * 8][tx] = W[(size_t)(kb + ty + i * 8) * Ndim + nb + tx];
    __syncthreads();
    #pragma unroll
    for (int i = 0; i < 4; i++) {
        const float v = t[tx][ty + i * 8];
        T[(size_t)(nb + ty + i * 8) * Kdim + kb + tx] = __float2half_rn(v);
    }
}

// ====== GEMM: CTA 128x128, warp 32x64, K-chunk 32, 3-stage ring ==========
#define GBM 128
#define GBN 128
#define GBK 32
#define SROW 20                       // padded row stride (u32) = 80B
#define GOP  (GBM * SROW * 4)         // one operand buffer: 10240 B
#define GA   0                        // A (3 buffers)
#define GB   (3 * GOP)                // W (3 buffers)
#define GEMM_SMEM (6 * GOP)           // 61440 B

struct GemmCtx {
    uint32_t sb;
    int warpM, warpN, lane;
    int mBase, nBase;
};

__device__ __forceinline__ void gemm_mainloop(
    const GemmCtx& g, const __half* Afg, const __half* Bg,
    int K, int tid, float acc[2][8][4])
{
    const int row = tid >> 1;
    const int seg = tid & 1;
    const uint32_t so = (row * SROW + seg * 8) * 4;
    const int nchunks = K / GBK;
    const uint32_t lrow = g.lane & 15;
    const uint32_t lhi  = (g.lane >> 4) << 4;

    auto stage = [&](int c, int buf) {
        const int k0 = c * GBK;
        const size_t ga = (size_t)(g.mBase + row) * K + k0 + seg * 16;
        const size_t gb = (size_t)(g.nBase + row) * K + k0 + seg * 16;
        cpa16(g.sb + GA + buf * GOP + so,      Afg + ga);
        cpa16(g.sb + GA + buf * GOP + so + 16, Afg + ga + 8);
        cpa16(g.sb + GB + buf * GOP + so,      Bg  + gb);
        cpa16(g.sb + GB + buf * GOP + so + 16, Bg  + gb + 8);
    };

    stage(0, 0); CP_COMMIT();
    stage(1, 1); CP_COMMIT();

    for (int c = 0; c < nchunks; c++) {
        if (c + 1 < nchunks) { CP_WAIT1(); } else { CP_WAIT0(); }
        __syncthreads();

        // prefetch chunk c+2 FIRST so loads overlap the whole compute phase
        if (c + 2 < nchunks) { stage(c + 2, (c + 2) % 3); CP_COMMIT(); }

        const uint32_t bA = g.sb + GA + (c % 3) * GOP;
        const uint32_t bB = g.sb + GB + (c % 3) * GOP;

        #pragma unroll
        for (int ks = 0; ks < 2; ks++) {
            const uint32_t kboff = ks * 32 + lhi;
            uint32_t ah[2][4];
            uint32_t bf[4][4];
            #pragma unroll
            for (int mt = 0; mt < 2; mt++) {
                const uint32_t ro = (g.warpM * 32 + mt * 16 + lrow) * (SROW * 4) + kboff;
                ldsm4(ah[mt], bA + ro);
            }
            #pragma unroll
            for (int reg = 0; reg < 4; reg++) {
                const uint32_t ro = (g.warpN * 64 + reg * 16 + lrow) * (SROW * 4) + kboff;
                ldsm4(bf[reg], bB + ro);
            }
            #pragma unroll
            for (int reg = 0; reg < 4; reg++)
                #pragma unroll
                for (int mt = 0; mt < 2; mt++)
                    #pragma unroll
                    for (int t = 0; t < 2; t++)
                        mma_f16(acc[mt][reg * 2 + t], ah[mt], bf[reg][t], bf[reg][t + 2]);
        }
    }
}

// ---- QKV GEMM with fused RoPE epilogue: Q/K/V single fp16 ---------------
__global__ __launch_bounds__(256, 2)
void mma_gemm_qkv(const __half* __restrict__ Afg, const __half* __restrict__ Bg,
                  const float* __restrict__ cosT, const float* __restrict__ sinT,
                  __half* __restrict__ Qf, __half* __restrict__ Kf,
                  __half* __restrict__ Vf)
{
    extern __shared__ char gsm[];
    const int tid = threadIdx.x;
    GemmCtx g;
    g.sb = smem_u32(gsm);
    g.lane = tid & 31;
    const int wid = tid >> 5;
    g.warpM = wid & 3;          // 4 warps in M (32 rows each)
    g.warpN = wid >> 2;         // 2 warps in N (64 cols each)
    g.mBase = blockIdx.y * GBM;
    g.nBase = blockIdx.x * GBN;

    float acc[2][8][4];
    #pragma unroll
    for (int a = 0; a < 2; a++)
        #pragma unroll
        for (int b = 0; b < 8; b++)
            #pragma unroll
            for (int c2 = 0; c2 < 4; c2++) acc[a][b][c2] = 0.f;

    gemm_mainloop(g, Afg, Bg, DD, tid, acc);

    // ---- fused epilogue: RoPE (Q,K); all single fp16 ----
    const int qrow = g.lane >> 2;
    const int qcol = (g.lane & 3) * 2;
    const float qscale = 0.125f * 1.4426950408889634f;  // HD^-0.5 * log2(e)

    const int colbase = g.nBase + g.warpN * 64;
    const int h3  = colbase >> 6;
    const int sec = h3 >> 4;                // 0=Q 1=K 2=V
    const int h   = h3 & 15;

    #pragma unroll
    for (int mt = 0; mt < 2; mt++) {
        const int r0 = g.mBase + g.warpM * 32 + mt * 16 + qrow;
        const int b  = r0 >> 11;          // /LL
        const int l0 = r0 & (LL - 1);
        const int l1 = l0 + 8;
        const size_t o0 = (((size_t)(b * HH + h) * LL) + l0) * HD;
        const size_t o1 = o0 + 8 * HD;
        #pragma unroll
        for (int n8 = 0; n8 < 4; n8++) {
            const int d = n8 * 8 + qcol;            // 0..31 within head

            const float a0 = acc[mt][n8][0], a1 = acc[mt][n8][1];
            const float a2 = acc[mt][n8][2], a3 = acc[mt][n8][3];
            const float b0 = acc[mt][n8 + 4][0], b1 = acc[mt][n8 + 4][1];
            const float b2 = acc[mt][n8 + 4][2], b3 = acc[mt][n8 + 4][3];

            if (sec == 2) {
                *(uint32_t*)(Vf + o0 + d)      = pack2h(a0, a1);
                *(uint32_t*)(Vf + o1 + d)      = pack2h(a2, a3);
                *(uint32_t*)(Vf + o0 + d + 32) = pack2h(b0, b1);
                *(uint32_t*)(Vf + o1 + d + 32) = pack2h(b2, b3);
            } else {
                const float2 cl0 = *(const float2*)(cosT + l0 * HD + d);
                const float2 ch0 = *(const float2*)(cosT + l0 * HD + d + 32);
                const float2 sl0 = *(const float2*)(sinT + l0 * HD + d);
                const float2 sh0 = *(const float2*)(sinT + l0 * HD + d + 32);
                const float2 cl1 = *(const float2*)(cosT + l1 * HD + d);
                const float2 ch1 = *(const float2*)(cosT + l1 * HD + d + 32);
                const float2 sl1 = *(const float2*)(sinT + l1 * HD + d);
                const float2 sh1 = *(const float2*)(sinT + l1 * HD + d + 32);

                // row l0
                float rl0 = a0 * cl0.x - b0 * sl0.x;
                float rl1 = a1 * cl0.y - b1 * sl0.y;
                float rh0 = b0 * ch0.x + a0 * sh0.x;
                float rh1 = b1 * ch0.y + a1 * sh0.y;
                // row l1
                float ql0 = a2 * cl1.x - b2 * sl1.x;
                float ql1 = a3 * cl1.y - b3 * sl1.y;
                float qh0 = b2 * ch1.x + a2 * sh1.x;
                float qh1 = b3 * ch1.y + a3 * sh1.y;

                if (sec == 0) {
                    *(uint32_t*)(Qf + o0 + d)      = pack2h(rl0 * qscale, rl1 * qscale);
                    *(uint32_t*)(Qf + o0 + d + 32) = pack2h(rh0 * qscale, rh1 * qscale);
                    *(uint32_t*)(Qf + o1 + d)      = pack2h(ql0 * qscale, ql1 * qscale);
                    *(uint32_t*)(Qf + o1 + d + 32) = pack2h(qh0 * qscale, qh1 * qscale);
                } else {
                    *(uint32_t*)(Kf + o0 + d)      = pack2h(rl0, rl1);
                    *(uint32_t*)(Kf + o0 + d + 32) = pack2h(rh0, rh1);
                    *(uint32_t*)(Kf + o1 + d)      = pack2h(ql0, ql1);
                    *(uint32_t*)(Kf + o1 + d + 32) = pack2h(qh0, qh1);
                }
            }
        }
    }
}

// ---- output projection GEMM (+bias), fp32 out ----------------------------
__global__ __launch_bounds__(256, 2)
void mma_gemm_bias(const __half* __restrict__ Afg, const __half* __restrict__ Bg,
                   const float* __restrict__ bias, float* __restrict__ C,
                   int Ntot, int K)
{
    extern __shared__ char gsm[];
    const int tid = threadIdx.x;
    GemmCtx g;
    g.sb = smem_u32(gsm);
    g.lane = tid & 31;
    const int wid = tid >> 5;
    g.warpM = wid & 3;
    g.warpN = wid >> 2;
    g.mBase = blockIdx.y * GBM;
    g.nBase = blockIdx.x * GBN;

    float acc[2][8][4];
    #pragma unroll
    for (int a = 0; a < 2; a++)
        #pragma unroll
        for (int b = 0; b < 8; b++)
            #pragma unroll
            for (int c2 = 0; c2 < 4; c2++) acc[a][b][c2] = 0.f;

    gemm_mainloop(g, Afg, Bg, K, tid, acc);

    const int qrow = g.lane >> 2;
    const int qcol = (g.lane & 3) * 2;
    #pragma unroll
    for (int mt = 0; mt < 2; mt++) {
        const int m0 = g.mBase + g.warpM * 32 + mt * 16 + qrow;
        #pragma unroll
        for (int n8 = 0; n8 < 8; n8++) {
            const int col = g.nBase + g.warpN * 64 + n8 * 8 + qcol;
            float2 v0, v1;
            v0.x = acc[mt][n8][0]; v0.y = acc[mt][n8][1];
            v1.x = acc[mt][n8][2]; v1.y = acc[mt][n8][3];
            const float b0 = bias[col], b1 = bias[col + 1];
            v0.x += b0; v0.y += b1;
            v1.x += b0; v1.y += b1;
            *(float2*)&C[(size_t)m0 * Ntot + col] = v0;
            *(float2*)&C[(size_t)(m0 + 8) * Ntot + col] = v1;
        }
    }
}

// --------------- flash attention (all single fp16, 3-stage KV ring) -------
#define RSTRIDE 144               // padded smem row (72 fp16)
#define ASQ  0                    // Q region: 128 * 144 = 18432
#define KVB  18432                // KV ring base (3 buffers)
#define KVSZ 18432                // one KV buffer (Kf, Vf @ 9216 each)
#define KOFF_V 9216
#define ATT_SMEM (KVB + 3 * KVSZ) // 73728

__global__ __launch_bounds__(256, 2)
void flash_attn(const __half* __restrict__ Qfg,
                const __half* __restrict__ Kfg, const __half* __restrict__ Vfg,
                __half* __restrict__ Of)
{
    extern __shared__ char smem[];
    const uint32_t sb = smem_u32(smem);
    const int tid = threadIdx.x, wid = tid >> 5, lane = tid & 31;
    const int qt = (LL / 128 - 1) - blockIdx.x;     // big tiles first
    const int bh = blockIdx.y;
    const int b = bh >> 4, h = bh & 15;
    const int q0 = qt * 128;
    const size_t base = (size_t)bh * LL * HD;

    const int ntiles = q0 / 64 + 2;

    auto stage_kv = [&](int t, int buf) {
        const int k0 = t * 64;
        const uint32_t bo = KVB + buf * KVSZ;
        #pragma unroll
        for (int j = 0; j < 2; j++) {
            const int item = j * 256 + tid;
            const int row = item >> 3, seg = item & 7;
            const size_t g = base + (size_t)(k0 + row) * HD + seg * 8;
            const uint32_t so = bo + row * RSTRIDE + seg * 16;
            cpa16(sb + so,           Kfg + g);
            cpa16(sb + so + KOFF_V,  Vfg + g);
        }
    };

    // ---- group 0: Q tile + KV tile 0; group 1: KV tile 1 ----
    {
        const int row = tid >> 1, seg = tid & 1;
        const size_t g = base + (size_t)(q0 + row) * HD + seg * 32;
        const uint32_t dq = sb + ASQ + row * RSTRIDE + seg * 64;
        #pragma unroll
        for (int i = 0; i < 4; i++)
            cpa16(dq + i * 16, Qfg + g + i * 8);
    }
    stage_kv(0, 0);
    CP_COMMIT();
    if (ntiles > 1) { stage_kv(1, 1); CP_COMMIT(); CP_WAIT1(); }
    else            { CP_WAIT0(); }
    __syncthreads();

    // ---- Q fragments (persistent; region never overwritten) ----
    uint32_t qf[4][4];
    {
        const uint32_t ro = (wid * 16 + (lane & 15)) * RSTRIDE + ((lane >> 4) << 4);
        #pragma unroll
        for (int ks = 0; ks < 4; ks++)
            ldsm4(qf[ks], sb + ASQ + ro + ks * 32);
    }

    float acc_o[8][4];
    #pragma unroll
    for (int j = 0; j < 8; j++)
        #pragma unroll
        for (int e = 0; e < 4; e++) acc_o[j][e] = 0.f;
    float m0 = -1e30f, m1 = -1e30f, l0 = 0.f, l1 = 0.f;

    const int qmin = q0 + wid * 16;
    const int r_lo = qmin + (lane >> 2);

    for (int t = 0; t < ntiles; t++) {
        const int k0 = t * 64;
        if (t > 0) {
            if (t + 1 < ntiles) { CP_WAIT1(); } else { CP_WAIT0(); }
            __syncthreads();
        }

        // prefetch tile t+2 FIRST so loads overlap the whole compute phase
        if (t + 2 < ntiles) { stage_kv(t + 2, (t + 2) % 3); CP_COMMIT(); }

        if (k0 <= qmin + 15) {                     // not fully masked for this warp
            const uint32_t kb = sb + KVB + (t % 3) * KVSZ;

            // ---- S = Q·Kᵀ (single term) ----
            float s[8][4];
            #pragma unroll
            for (int j = 0; j < 8; j++)
                #pragma unroll
                for (int e = 0; e < 4; e++) s[j][e] = 0.f;

            #pragma unroll
            for (int ks = 0; ks < 4; ks++) {
                #pragma unroll
                for (int kp = 0; kp < 2; kp++) {
                    uint32_t kf[2][4];
                    #pragma unroll
                    for (int i = 0; i < 2; i++) {
                        const int np = kp * 2 + i;
                        const uint32_t ro = (np * 16 + (lane & 15)) * RSTRIDE +
                                            ((lane >> 4) << 4) + ks * 32;
                        ldsm4(kf[i], kb + ro);
                    }
                    #pragma unroll
                    for (int i = 0; i < 2; i++) {
                        const int np = kp * 2 + i;
                        mma_f16(s[2 * np],     qf[ks], kf[i][0], kf[i][2]);
                        mma_f16(s[2 * np + 1], qf[ks], kf[i][1], kf[i][3]);
                    }
                }
            }

            // ---- causal mask ----
            if (k0 + 63 > qmin) {
                #pragma unroll
                for (int j = 0; j < 8; j++) {
                    const int key = k0 + j * 8 + (lane & 3) * 2;
                    if (key     > r_lo)     s[j][0] = -1e30f;
                    if (key + 1 > r_lo)     s[j][1] = -1e30f;
                    if (key     > r_lo + 8) s[j][2] = -1e30f;
                    if (key + 1 > r_lo + 8) s[j][3] = -1e30f;
                }
            }

            // ---- online softmax (log2 domain) ----
            float rm0 = -1e30f, rm1 = -1e30f;
            #pragma unroll
            for (int j = 0; j < 8; j++) {
                rm0 = fmaxf(rm0, fmaxf(s[j][0], s[j][1]));
                rm1 = fmaxf(rm1, fmaxf(s[j][2], s[j][3]));
            }
            rm0 = fmaxf(rm0, __shfl_xor_sync(0xffffffff, rm0, 1));
            rm0 = fmaxf(rm0, __shfl_xor_sync(0xffffffff, rm0, 2));
            rm1 = fmaxf(rm1, __shfl_xor_sync(0xffffffff, rm1, 1));
            rm1 = fmaxf(rm1, __shfl_xor_sync(0xffffffff, rm1, 2));

            const float mn0 = fmaxf(m0, rm0), mn1 = fmaxf(m1, rm1);
            const float c0 = fexp2(m0 - mn0), c1 = fexp2(m1 - mn1);
            m0 = mn0; m1 = mn1;
            l0 *= c0; l1 *= c1;
            #pragma unroll
            for (int j = 0; j < 8; j++) {
                acc_o[j][0] *= c0; acc_o[j][1] *= c0;
                acc_o[j][2] *= c1; acc_o[j][3] *= c1;
            }

            #pragma unroll
            for (int j = 0; j < 8; j++) {
                s[j][0] = fexp2(s[j][0] - m0);
                s[j][1] = fexp2(s[j][1] - m0);
                s[j][2] = fexp2(s[j][2] - m1);
                s[j][3] = fexp2(s[j][3] - m1);
                l0 += s[j][0] + s[j][1];
                l1 += s[j][2] + s[j][3];
            }

            // ---- O += P·V (P single fp16) ----
            #pragma unroll
            for (int ks = 0; ks < 4; ks++) {
                uint32_t pf[4];
                const int j0 = 2 * ks, j1 = 2 * ks + 1;
                pf[0] = pack2h(s[j0][0], s[j0][1]);
                pf[1] = pack2h(s[j0][2], s[j0][3]);
                pf[2] = pack2h(s[j1][0], s[j1][1]);
                pf[3] = pack2h(s[j1][2], s[j1][3]);

                #pragma unroll
                for (int vp = 0; vp < 2; vp++) {
                    uint32_t vf[2][4];
                    #pragma unroll
                    for (int i = 0; i < 2; i++) {
                        const int np = vp * 2 + i;
                        const int g = lane >> 3;
                        const uint32_t vrow = ks * 16 + (g & 1) * 8 + (lane & 7);
                        const uint32_t ro = vrow * RSTRIDE + np * 32 + (g >> 1) * 16;
                        ldsm4t(vf[i], kb + KOFF_V + ro);
                    }
                    #pragma unroll
                    for (int i = 0; i < 2; i++) {
                        const int np = vp * 2 + i;
                        mma_f16(acc_o[2 * np],     pf, vf[i][0], vf[i][1]);
                        mma_f16(acc_o[2 * np + 1], pf, vf[i][2], vf[i][3]);
                    }
                }
            }
        }
    }

    // ---- epilogue: normalize, write single fp16 [B*L, 1024] ----
    l0 += __shfl_xor_sync(0xffffffff, l0, 1);
    l0 += __shfl_xor_sync(0xffffffff, l0, 2);
    l1 += __shfl_xor_sync(0xffffffff, l1, 1);
    l1 += __shfl_xor_sync(0xffffffff, l1, 2);
    const float inv0 = 1.0f / l0, inv1 = 1.0f / l1;

    const size_t row0 = (size_t)(b * LL + q0 + wid * 16 + (lane >> 2));
    const size_t row1 = row0 + 8;
    const int colbase = h * HD + (lane & 3) * 2;
    #pragma unroll
    for (int j = 0; j < 8; j++) {
        const int col = colbase + j * 8;
        *(uint32_t*)(Of + row0 * DD + col) = pack2h(acc_o[j][0] * inv0, acc_o[j][1] * inv0);
        *(uint32_t*)(Of + row1 * DD + col) = pack2h(acc_o[j][2] * inv1, acc_o[j][3] * inv1);
    }
}

// -------------------------------------------------------------------------
extern "C" void kernel_launch(void* const* d_in, const int* in_sizes, int n_in,
                              void* d_out, int out_size)
{
    const float* x        = (const float*)d_in[0];
    const float* rope_cos = (const float*)d_in[1];
    const float* rope_sin = (const float*)d_in[2];
    const float* W_qkv    = (const float*)d_in[3];
    const float* W_out    = (const float*)d_in[4];
    const float* b_out    = (const float*)d_in[5];
    float* out = (float*)d_out;

    __half *xf, *wq, *wo, *attf, *Qf, *Kf, *Vf;
    cudaGetSymbolAddress((void**)&xf,   g_xf);
    cudaGetSymbolAddress((void**)&wq,   g_wqkvT);
    cudaGetSymbolAddress((void**)&wo,   g_woutT);
    cudaGetSymbolAddress((void**)&attf, g_attf);
    cudaGetSymbolAddress((void**)&Qf,   g_Qf);
    cudaGetSymbolAddress((void**)&Kf,   g_Kf);
    cudaGetSymbolAddress((void**)&Vf,   g_Vf);

    cudaFuncSetAttribute(flash_attn,    cudaFuncAttributeMaxDynamicSharedMemorySize, ATT_SMEM);
    cudaFuncSetAttribute(mma_gemm_qkv,  cudaFuncAttributeMaxDynamicSharedMemorySize, GEMM_SMEM);
    cudaFuncSetAttribute(mma_gemm_bias, cudaFuncAttributeMaxDynamicSharedMemorySize, GEMM_SMEM);

    // 0) operand conversion (all single fp16)
    conv_half<<<(MROWS * DD / 4 + 255) / 256, 256>>>(x, xf, MROWS * DD / 4);
    conv_halfT<<<dim3(NQKV / 32, DD / 32), dim3(32, 8)>>>(W_qkv, wq, DD, NQKV);
    conv_halfT<<<dim3(DD / 32, DD / 32),   dim3(32, 8)>>>(W_out, wo, DD, DD);

    // 1) QKV projection + fused RoPE epilogue -> Qf, Kf, Vf [B,H,L,HD]
    mma_gemm_qkv<<<dim3(NQKV / GBN, MROWS / GBM), 256, GEMM_SMEM>>>(
        xf, wq, rope_cos, rope_sin, Qf, Kf, Vf);

    // 2) flash attention (all single fp16) -> attf
    flash_attn<<<dim3(LL / 128, BB * HH), 256, ATT_SMEM>>>(
        Qf, Kf, Vf, attf);

    // 3) output projection + bias
    mma_gemm_bias<<<dim3(DD / GBN, MROWS / GBM), 256, GEMM_SMEM>>>(
        attf, wo, b_out, out, DD, DD);
}

// round 15
// speedup vs baseline: 1.0604x; 1.0347x over previous
#include <cuda_runtime.h>
#include <cuda_fp16.h>
#include <cstdint>

// Problem constants
#define BB 2
#define LL 2048
#define DD 1024
#define HH 16
#define HD 64
#define NQKV 3072        // 3*H*HD
#define MROWS (BB*LL)    // 4096

// ---------------- scratch (device globals; no allocations allowed) -------
__device__ __half g_xf[MROWS * DD];               // x single fp16
__device__ __half g_wqkvT[NQKV * DD];             // [N][K] single
__device__ __half g_woutT[DD * DD];               // [N][K] single

// attention operands, fp16 single, [B,H,L,HD] (Q scaled by 0.125*log2e)
__device__ __half g_Qf[BB * HH * LL * HD];
__device__ __half g_Kf[BB * HH * LL * HD];
__device__ __half g_Vf[BB * HH * LL * HD];
__device__ __half g_attf[MROWS * DD];             // [B*L, 1024] single

// ==================== helpers =============================================
__device__ __forceinline__ uint32_t smem_u32(const void* p) {
    uint32_t a;
    asm("{ .reg .u64 t; cvta.to.shared.u64 t, %1; cvt.u32.u64 %0, t; }"
        : "=r"(a) : "l"(p));
    return a;
}

// pack two floats -> half2 reg (a in low half)
__device__ __forceinline__ uint32_t pack2h(float a, float b) {
    __half2 h = __floats2half2_rn(a, b);
    return *(uint32_t*)&h;
}

__device__ __forceinline__ void ldsm4(uint32_t* r, uint32_t addr) {
    asm volatile("ldmatrix.sync.aligned.m8n8.x4.shared.b16 {%0,%1,%2,%3}, [%4];"
                 : "=r"(r[0]), "=r"(r[1]), "=r"(r[2]), "=r"(r[3]) : "r"(addr));
}

__device__ __forceinline__ void ldsm4t(uint32_t* r, uint32_t addr) {
    asm volatile("ldmatrix.sync.aligned.m8n8.x4.trans.shared.b16 {%0,%1,%2,%3}, [%4];"
                 : "=r"(r[0]), "=r"(r[1]), "=r"(r[2]), "=r"(r[3]) : "r"(addr));
}

__device__ __forceinline__ void mma_f16(float* d, const uint32_t* a, uint32_t b0, uint32_t b1) {
    asm volatile(
        "mma.sync.aligned.m16n8k16.row.col.f32.f16.f16.f32 "
        "{%0,%1,%2,%3}, {%4,%5,%6,%7}, {%8,%9}, {%0,%1,%2,%3};"
        : "+f"(d[0]), "+f"(d[1]), "+f"(d[2]), "+f"(d[3])
        : "r"(a[0]), "r"(a[1]), "r"(a[2]), "r"(a[3]), "r"(b0), "r"(b1));
}

// cp.async with L1 caching (.ca)
__device__ __forceinline__ void cpa16(uint32_t dst, const void* src) {
    asm volatile("cp.async.ca.shared.global [%0], [%1], 16;" :: "r"(dst), "l"(src));
}
#define CP_COMMIT() asm volatile("cp.async.commit_group;" ::: "memory")
#define CP_WAIT0()  asm volatile("cp.async.wait_group 0;" ::: "memory")
#define CP_WAIT1()  asm volatile("cp.async.wait_group 1;" ::: "memory")

// fast exp2 on FMA pipe (x <= 0 expected; clamped at -120)
__device__ __forceinline__ float fexp2(float x) {
    x = fmaxf(x, -120.0f);
    float n = floorf(x);
    float f = x - n;
    float p = 1.5404226e-4f;
    p = fmaf(p, f, 1.3333558e-3f);
    p = fmaf(p, f, 9.6181291e-3f);
    p = fmaf(p, f, 5.5504109e-2f);
    p = fmaf(p, f, 2.4022651e-1f);
    p = fmaf(p, f, 6.9314718e-1f);
    p = fmaf(p, f, 1.0f);
    return __int_as_float(__float_as_int(p) + (((int)n) << 23));
}

// ==================== fused conversion kernel =============================
// blocks [0, 4096)            : x fp32 -> xf fp16 (float4 per thread)
// blocks [4096, 4096+3072)    : W_qkv [K][N] -> wqkvT [N][K] fp16
// blocks [7168, 7168+1024)    : W_out [K][N] -> woutT [N][K] fp16
#define CONV_XBLKS  (MROWS * DD / 4 / 256)       // 4096
#define CONV_QBLKS  ((NQKV / 32) * (DD / 32))    // 3072
#define CONV_OBLKS  ((DD / 32) * (DD / 32))      // 1024

__global__ void conv_all(const float* __restrict__ x, __half* __restrict__ xf,
                         const float* __restrict__ Wq, __half* __restrict__ WqT,
                         const float* __restrict__ Wo, __half* __restrict__ WoT)
{
    const int bid = blockIdx.x;
    const int tid = threadIdx.x;

    if (bid < CONV_XBLKS) {
        const int i = bid * 256 + tid;
        float4 v = ((const float4*)x)[i];
        __half h[4];
        h[0] = __float2half_rn(v.x);
        h[1] = __float2half_rn(v.y);
        h[2] = __float2half_rn(v.z);
        h[3] = __float2half_rn(v.w);
        ((uint2*)xf)[i] = *(uint2*)h;
        return;
    }

    // transpose path: 32x32 tile, 256 threads (tx 0..31, ty 0..7)
    const float* W;
    __half* T;
    int nb, kb, Ndim;
    if (bid < CONV_XBLKS + CONV_QBLKS) {
        const int b2 = bid - CONV_XBLKS;
        W = Wq; T = WqT; Ndim = NQKV;
        nb = (b2 % (NQKV / 32)) * 32;
        kb = (b2 / (NQKV / 32)) * 32;
    } else {
        const int b3 = bid - CONV_XBLKS - CONV_QBLKS;
        W = Wo; T = WoT; Ndim = DD;
        nb = (b3 % (DD / 32)) * 32;
        kb = (b3 / (DD / 32)) * 32;
    }

    __shared__ float t[32][33];
    const int tx = tid & 31, ty = tid >> 5;
    #pragma unroll
    for (int i = 0; i < 4; i++)
        t[ty + i * 8][tx] = W[(size_t)(kb + ty + i * 8) * Ndim + nb + tx];
    __syncthreads();
    #pragma unroll
    for (int i = 0; i < 4; i++) {
        const float v = t[tx][ty + i * 8];
        T[(size_t)(nb + ty + i * 8) * DD + kb + tx] = __float2half_rn(v);
    }
}

// ====== GEMM: CTA 128x128, warp 32x64, K-chunk 32, 3-stage ring ==========
#define GBM 128
#define GBN 128
#define GBK 32
#define SROW 20                       // padded row stride (u32) = 80B
#define GOP  (GBM * SROW * 4)         // one operand buffer: 10240 B
#define GA   0                        // A (3 buffers)
#define GB   (3 * GOP)                // W (3 buffers)
#define GEMM_SMEM (6 * GOP)           // 61440 B

struct GemmCtx {
    uint32_t sb;
    int warpM, warpN, lane;
    int mBase, nBase;
};

__device__ __forceinline__ void gemm_mainloop(
    const GemmCtx& g, const __half* Afg, const __half* Bg,
    int K, int tid, float acc[2][8][4])
{
    const int row = tid >> 1;
    const int seg = tid & 1;
    const uint32_t so = (row * SROW + seg * 8) * 4;
    const int nchunks = K / GBK;
    const uint32_t lrow = g.lane & 15;
    const uint32_t lhi  = (g.lane >> 4) << 4;

    auto stage = [&](int c, int buf) {
        const int k0 = c * GBK;
        const size_t ga = (size_t)(g.mBase + row) * K + k0 + seg * 16;
        const size_t gb = (size_t)(g.nBase + row) * K + k0 + seg * 16;
        cpa16(g.sb + GA + buf * GOP + so,      Afg + ga);
        cpa16(g.sb + GA + buf * GOP + so + 16, Afg + ga + 8);
        cpa16(g.sb + GB + buf * GOP + so,      Bg  + gb);
        cpa16(g.sb + GB + buf * GOP + so + 16, Bg  + gb + 8);
    };

    stage(0, 0); CP_COMMIT();
    stage(1, 1); CP_COMMIT();

    for (int c = 0; c < nchunks; c++) {
        if (c + 1 < nchunks) { CP_WAIT1(); } else { CP_WAIT0(); }
        __syncthreads();

        const uint32_t bA = g.sb + GA + (c % 3) * GOP;
        const uint32_t bB = g.sb + GB + (c % 3) * GOP;

        #pragma unroll
        for (int ks = 0; ks < 2; ks++) {
            const uint32_t kboff = ks * 32 + lhi;
            uint32_t ah[2][4];
            uint32_t bf[4][4];
            #pragma unroll
            for (int mt = 0; mt < 2; mt++) {
                const uint32_t ro = (g.warpM * 32 + mt * 16 + lrow) * (SROW * 4) + kboff;
                ldsm4(ah[mt], bA + ro);
            }
            #pragma unroll
            for (int reg = 0; reg < 4; reg++) {
                const uint32_t ro = (g.warpN * 64 + reg * 16 + lrow) * (SROW * 4) + kboff;
                ldsm4(bf[reg], bB + ro);
            }
            #pragma unroll
            for (int reg = 0; reg < 4; reg++)
                #pragma unroll
                for (int mt = 0; mt < 2; mt++)
                    #pragma unroll
                    for (int t = 0; t < 2; t++)
                        mma_f16(acc[mt][reg * 2 + t], ah[mt], bf[reg][t], bf[reg][t + 2]);
        }

        if (c + 2 < nchunks) { stage(c + 2, (c + 2) % 3); CP_COMMIT(); }
    }
}

// ---- QKV GEMM with fused RoPE epilogue: Q/K/V single fp16 ---------------
__global__ __launch_bounds__(256, 2)
void mma_gemm_qkv(const __half* __restrict__ Afg, const __half* __restrict__ Bg,
                  const float* __restrict__ cosT, const float* __restrict__ sinT,
                  __half* __restrict__ Qf, __half* __restrict__ Kf,
                  __half* __restrict__ Vf)
{
    extern __shared__ char gsm[];
    const int tid = threadIdx.x;
    GemmCtx g;
    g.sb = smem_u32(gsm);
    g.lane = tid & 31;
    const int wid = tid >> 5;
    g.warpM = wid & 3;          // 4 warps in M (32 rows each)
    g.warpN = wid >> 2;         // 2 warps in N (64 cols each)
    g.mBase = blockIdx.y * GBM;
    g.nBase = blockIdx.x * GBN;

    float acc[2][8][4];
    #pragma unroll
    for (int a = 0; a < 2; a++)
        #pragma unroll
        for (int b = 0; b < 8; b++)
            #pragma unroll
            for (int c2 = 0; c2 < 4; c2++) acc[a][b][c2] = 0.f;

    gemm_mainloop(g, Afg, Bg, DD, tid, acc);

    // ---- fused epilogue: RoPE (Q,K); all single fp16 ----
    const int qrow = g.lane >> 2;
    const int qcol = (g.lane & 3) * 2;
    const float qscale = 0.125f * 1.4426950408889634f;  // HD^-0.5 * log2(e)

    const int colbase = g.nBase + g.warpN * 64;
    const int h3  = colbase >> 6;
    const int sec = h3 >> 4;                // 0=Q 1=K 2=V
    const int h   = h3 & 15;

    #pragma unroll
    for (int mt = 0; mt < 2; mt++) {
        const int r0 = g.mBase + g.warpM * 32 + mt * 16 + qrow;
        const int b  = r0 >> 11;          // /LL
        const int l0 = r0 & (LL - 1);
        const int l1 = l0 + 8;
        const size_t o0 = (((size_t)(b * HH + h) * LL) + l0) * HD;
        const size_t o1 = o0 + 8 * HD;
        #pragma unroll
        for (int n8 = 0; n8 < 4; n8++) {
            const int d = n8 * 8 + qcol;            // 0..31 within head

            const float a0 = acc[mt][n8][0], a1 = acc[mt][n8][1];
            const float a2 = acc[mt][n8][2], a3 = acc[mt][n8][3];
            const float b0 = acc[mt][n8 + 4][0], b1 = acc[mt][n8 + 4][1];
            const float b2 = acc[mt][n8 + 4][2], b3 = acc[mt][n8 + 4][3];

            if (sec == 2) {
                *(uint32_t*)(Vf + o0 + d)      = pack2h(a0, a1);
                *(uint32_t*)(Vf + o1 + d)      = pack2h(a2, a3);
                *(uint32_t*)(Vf + o0 + d + 32) = pack2h(b0, b1);
                *(uint32_t*)(Vf + o1 + d + 32) = pack2h(b2, b3);
            } else {
                const float2 cl0 = *(const float2*)(cosT + l0 * HD + d);
                const float2 ch0 = *(const float2*)(cosT + l0 * HD + d + 32);
                const float2 sl0 = *(const float2*)(sinT + l0 * HD + d);
                const float2 sh0 = *(const float2*)(sinT + l0 * HD + d + 32);
                const float2 cl1 = *(const float2*)(cosT + l1 * HD + d);
                const float2 ch1 = *(const float2*)(cosT + l1 * HD + d + 32);
                const float2 sl1 = *(const float2*)(sinT + l1 * HD + d);
                const float2 sh1 = *(const float2*)(sinT + l1 * HD + d + 32);

                // row l0
                float rl0 = a0 * cl0.x - b0 * sl0.x;
                float rl1 = a1 * cl0.y - b1 * sl0.y;
                float rh0 = b0 * ch0.x + a0 * sh0.x;
                float rh1 = b1 * ch0.y + a1 * sh0.y;
                // row l1
                float ql0 = a2 * cl1.x - b2 * sl1.x;
                float ql1 = a3 * cl1.y - b3 * sl1.y;
                float qh0 = b2 * ch1.x + a2 * sh1.x;
                float qh1 = b3 * ch1.y + a3 * sh1.y;

                if (sec == 0) {
                    *(uint32_t*)(Qf + o0 + d)      = pack2h(rl0 * qscale, rl1 * qscale);
                    *(uint32_t*)(Qf + o0 + d + 32) = pack2h(rh0 * qscale, rh1 * qscale);
                    *(uint32_t*)(Qf + o1 + d)      = pack2h(ql0 * qscale, ql1 * qscale);
                    *(uint32_t*)(Qf + o1 + d + 32) = pack2h(qh0 * qscale, qh1 * qscale);
                } else {
                    *(uint32_t*)(Kf + o0 + d)      = pack2h(rl0, rl1);
                    *(uint32_t*)(Kf + o0 + d + 32) = pack2h(rh0, rh1);
                    *(uint32_t*)(Kf + o1 + d)      = pack2h(ql0, ql1);
                    *(uint32_t*)(Kf + o1 + d + 32) = pack2h(qh0, qh1);
                }
            }
        }
    }
}

// ---- output projection GEMM (+bias), fp32 out ----------------------------
__global__ __launch_bounds__(256, 2)
void mma_gemm_bias(const __half* __restrict__ Afg, const __half* __restrict__ Bg,
                   const float* __restrict__ bias, float* __restrict__ C,
                   int Ntot, int K)
{
    extern __shared__ char gsm[];
    const int tid = threadIdx.x;
    GemmCtx g;
    g.sb = smem_u32(gsm);
    g.lane = tid & 31;
    const int wid = tid >> 5;
    g.warpM = wid & 3;
    g.warpN = wid >> 2;
    g.mBase = blockIdx.y * GBM;
    g.nBase = blockIdx.x * GBN;

    float acc[2][8][4];
    #pragma unroll
    for (int a = 0; a < 2; a++)
        #pragma unroll
        for (int b = 0; b < 8; b++)
            #pragma unroll
            for (int c2 = 0; c2 < 4; c2++) acc[a][b][c2] = 0.f;

    gemm_mainloop(g, Afg, Bg, K, tid, acc);

    const int qrow = g.lane >> 2;
    const int qcol = (g.lane & 3) * 2;
    #pragma unroll
    for (int mt = 0; mt < 2; mt++) {
        const int m0 = g.mBase + g.warpM * 32 + mt * 16 + qrow;
        #pragma unroll
        for (int n8 = 0; n8 < 8; n8++) {
            const int col = g.nBase + g.warpN * 64 + n8 * 8 + qcol;
            float2 v0, v1;
            v0.x = acc[mt][n8][0]; v0.y = acc[mt][n8][1];
            v1.x = acc[mt][n8][2]; v1.y = acc[mt][n8][3];
            const float b0 = bias[col], b1 = bias[col + 1];
            v0.x += b0; v0.y += b1;
            v1.x += b0; v1.y += b1;
            *(float2*)&C[(size_t)m0 * Ntot + col] = v0;
            *(float2*)&C[(size_t)(m0 + 8) * Ntot + col] = v1;
        }
    }
}

// --------------- flash attention (all single fp16, 3-stage KV ring) -------
#define RSTRIDE 144               // padded smem row (72 fp16)
#define ASQ  0                    // Q region: 128 * 144 = 18432
#define KVB  18432                // KV ring base (3 buffers)
#define KVSZ 18432                // one KV buffer (Kf, Vf @ 9216 each)
#define KOFF_V 9216
#define ATT_SMEM (KVB + 3 * KVSZ) // 73728

__global__ __launch_bounds__(256, 2)
void flash_attn(const __half* __restrict__ Qfg,
                const __half* __restrict__ Kfg, const __half* __restrict__ Vfg,
                __half* __restrict__ Of)
{
    extern __shared__ char smem[];
    const uint32_t sb = smem_u32(smem);
    const int tid = threadIdx.x, wid = tid >> 5, lane = tid & 31;
    const int qt = (LL / 128 - 1) - blockIdx.x;     // big tiles first
    const int bh = blockIdx.y;
    const int b = bh >> 4, h = bh & 15;
    const int q0 = qt * 128;
    const size_t base = (size_t)bh * LL * HD;

    const int ntiles = q0 / 64 + 2;

    auto stage_kv = [&](int t, int buf) {
        const int k0 = t * 64;
        const uint32_t bo = KVB + buf * KVSZ;
        #pragma unroll
        for (int j = 0; j < 2; j++) {
            const int item = j * 256 + tid;
            const int row = item >> 3, seg = item & 7;
            const size_t g = base + (size_t)(k0 + row) * HD + seg * 8;
            const uint32_t so = bo + row * RSTRIDE + seg * 16;
            cpa16(sb + so,           Kfg + g);
            cpa16(sb + so + KOFF_V,  Vfg + g);
        }
    };

    // ---- group 0: Q tile + KV tile 0; group 1: KV tile 1 ----
    {
        const int row = tid >> 1, seg = tid & 1;
        const size_t g = base + (size_t)(q0 + row) * HD + seg * 32;
        const uint32_t dq = sb + ASQ + row * RSTRIDE + seg * 64;
        #pragma unroll
        for (int i = 0; i < 4; i++)
            cpa16(dq + i * 16, Qfg + g + i * 8);
    }
    stage_kv(0, 0);
    CP_COMMIT();
    if (ntiles > 1) { stage_kv(1, 1); CP_COMMIT(); CP_WAIT1(); }
    else            { CP_WAIT0(); }
    __syncthreads();

    // ---- Q fragments (persistent; region never overwritten) ----
    uint32_t qf[4][4];
    {
        const uint32_t ro = (wid * 16 + (lane & 15)) * RSTRIDE + ((lane >> 4) << 4);
        #pragma unroll
        for (int ks = 0; ks < 4; ks++)
            ldsm4(qf[ks], sb + ASQ + ro + ks * 32);
    }

    float acc_o[8][4];
    #pragma unroll
    for (int j = 0; j < 8; j++)
        #pragma unroll
        for (int e = 0; e < 4; e++) acc_o[j][e] = 0.f;
    float m0 = -1e30f, m1 = -1e30f, l0 = 0.f, l1 = 0.f;

    const int qmin = q0 + wid * 16;
    const int r_lo = qmin + (lane >> 2);

    for (int t = 0; t < ntiles; t++) {
        const int k0 = t * 64;
        if (t > 0) {
            if (t + 1 < ntiles) { CP_WAIT1(); } else { CP_WAIT0(); }
            __syncthreads();
        }

        if (k0 <= qmin + 15) {                     // not fully masked for this warp
            const uint32_t kb = sb + KVB + (t % 3) * KVSZ;

            // ---- S = Q·Kᵀ (single term) ----
            float s[8][4];
            #pragma unroll
            for (int j = 0; j < 8; j++)
                #pragma unroll
                for (int e = 0; e < 4; e++) s[j][e] = 0.f;

            #pragma unroll
            for (int ks = 0; ks < 4; ks++) {
                #pragma unroll
                for (int kp = 0; kp < 2; kp++) {
                    uint32_t kf[2][4];
                    #pragma unroll
                    for (int i = 0; i < 2; i++) {
                        const int np = kp * 2 + i;
                        const uint32_t ro = (np * 16 + (lane & 15)) * RSTRIDE +
                                            ((lane >> 4) << 4) + ks * 32;
                        ldsm4(kf[i], kb + ro);
                    }
                    #pragma unroll
                    for (int i = 0; i < 2; i++) {
                        const int np = kp * 2 + i;
                        mma_f16(s[2 * np],     qf[ks], kf[i][0], kf[i][2]);
                        mma_f16(s[2 * np + 1], qf[ks], kf[i][1], kf[i][3]);
                    }
                }
            }

            // ---- causal mask ----
            if (k0 + 63 > qmin) {
                #pragma unroll
                for (int j = 0; j < 8; j++) {
                    const int key = k0 + j * 8 + (lane & 3) * 2;
                    if (key     > r_lo)     s[j][0] = -1e30f;
                    if (key + 1 > r_lo)     s[j][1] = -1e30f;
                    if (key     > r_lo + 8) s[j][2] = -1e30f;
                    if (key + 1 > r_lo + 8) s[j][3] = -1e30f;
                }
            }

            // ---- online softmax (log2 domain) ----
            float rm0 = -1e30f, rm1 = -1e30f;
            #pragma unroll
            for (int j = 0; j < 8; j++) {
                rm0 = fmaxf(rm0, fmaxf(s[j][0], s[j][1]));
                rm1 = fmaxf(rm1, fmaxf(s[j][2], s[j][3]));
            }
            rm0 = fmaxf(rm0, __shfl_xor_sync(0xffffffff, rm0, 1));
            rm0 = fmaxf(rm0, __shfl_xor_sync(0xffffffff, rm0, 2));
            rm1 = fmaxf(rm1, __shfl_xor_sync(0xffffffff, rm1, 1));
            rm1 = fmaxf(rm1, __shfl_xor_sync(0xffffffff, rm1, 2));

            const float mn0 = fmaxf(m0, rm0), mn1 = fmaxf(m1, rm1);
            const float c0 = fexp2(m0 - mn0), c1 = fexp2(m1 - mn1);
            m0 = mn0; m1 = mn1;
            l0 *= c0; l1 *= c1;
            #pragma unroll
            for (int j = 0; j < 8; j++) {
                acc_o[j][0] *= c0; acc_o[j][1] *= c0;
                acc_o[j][2] *= c1; acc_o[j][3] *= c1;
            }

            #pragma unroll
            for (int j = 0; j < 8; j++) {
                s[j][0] = fexp2(s[j][0] - m0);
                s[j][1] = fexp2(s[j][1] - m0);
                s[j][2] = fexp2(s[j][2] - m1);
                s[j][3] = fexp2(s[j][3] - m1);
                l0 += s[j][0] + s[j][1];
                l1 += s[j][2] + s[j][3];
            }

            // ---- O += P·V (P single fp16) ----
            #pragma unroll
            for (int ks = 0; ks < 4; ks++) {
                uint32_t pf[4];
                const int j0 = 2 * ks, j1 = 2 * ks + 1;
                pf[0] = pack2h(s[j0][0], s[j0][1]);
                pf[1] = pack2h(s[j0][2], s[j0][3]);
                pf[2] = pack2h(s[j1][0], s[j1][1]);
                pf[3] = pack2h(s[j1][2], s[j1][3]);

                #pragma unroll
                for (int vp = 0; vp < 2; vp++) {
                    uint32_t vf[2][4];
                    #pragma unroll
                    for (int i = 0; i < 2; i++) {
                        const int np = vp * 2 + i;
                        const int g = lane >> 3;
                        const uint32_t vrow = ks * 16 + (g & 1) * 8 + (lane & 7);
                        const uint32_t ro = vrow * RSTRIDE + np * 32 + (g >> 1) * 16;
                        ldsm4t(vf[i], kb + KOFF_V + ro);
                    }
                    #pragma unroll
                    for (int i = 0; i < 2; i++) {
                        const int np = vp * 2 + i;
                        mma_f16(acc_o[2 * np],     pf, vf[i][0], vf[i][1]);
                        mma_f16(acc_o[2 * np + 1], pf, vf[i][2], vf[i][3]);
                    }
                }
            }
        }

        if (t + 2 < ntiles) { stage_kv(t + 2, (t + 2) % 3); CP_COMMIT(); }
    }

    // ---- epilogue: normalize, write single fp16 [B*L, 1024] ----
    l0 += __shfl_xor_sync(0xffffffff, l0, 1);
    l0 += __shfl_xor_sync(0xffffffff, l0, 2);
    l1 += __shfl_xor_sync(0xffffffff, l1, 1);
    l1 += __shfl_xor_sync(0xffffffff, l1, 2);
    const float inv0 = 1.0f / l0, inv1 = 1.0f / l1;

    const size_t row0 = (size_t)(b * LL + q0 + wid * 16 + (lane >> 2));
    const size_t row1 = row0 + 8;
    const int colbase = h * HD + (lane & 3) * 2;
    #pragma unroll
    for (int j = 0; j < 8; j++) {
        const int col = colbase + j * 8;
        *(uint32_t*)(Of + row0 * DD + col) = pack2h(acc_o[j][0] * inv0, acc_o[j][1] * inv0);
        *(uint32_t*)(Of + row1 * DD + col) = pack2h(acc_o[j][2] * inv1, acc_o[j][3] * inv1);
    }
}

// -------------------------------------------------------------------------
extern "C" void kernel_launch(void* const* d_in, const int* in_sizes, int n_in,
                              void* d_out, int out_size)
{
    const float* x        = (const float*)d_in[0];
    const float* rope_cos = (const float*)d_in[1];
    const float* rope_sin = (const float*)d_in[2];
    const float* W_qkv    = (const float*)d_in[3];
    const float* W_out    = (const float*)d_in[4];
    const float* b_out    = (const float*)d_in[5];
    float* out = (float*)d_out;

    __half *xf, *wq, *wo, *attf, *Qf, *Kf, *Vf;
    cudaGetSymbolAddress((void**)&xf,   g_xf);
    cudaGetSymbolAddress((void**)&wq,   g_wqkvT);
    cudaGetSymbolAddress((void**)&wo,   g_woutT);
    cudaGetSymbolAddress((void**)&attf, g_attf);
    cudaGetSymbolAddress((void**)&Qf,   g_Qf);
    cudaGetSymbolAddress((void**)&Kf,   g_Kf);
    cudaGetSymbolAddress((void**)&Vf,   g_Vf);

    cudaFuncSetAttribute(flash_attn,    cudaFuncAttributeMaxDynamicSharedMemorySize, ATT_SMEM);
    cudaFuncSetAttribute(mma_gemm_qkv,  cudaFuncAttributeMaxDynamicSharedMemorySize, GEMM_SMEM);
    cudaFuncSetAttribute(mma_gemm_bias, cudaFuncAttributeMaxDynamicSharedMemorySize, GEMM_SMEM);

    // 0) fused operand conversion (x, W_qkvT, W_outT) in ONE launch
    conv_all<<<CONV_XBLKS + CONV_QBLKS + CONV_OBLKS, 256>>>(
        x, xf, W_qkv, wq, W_out, wo);

    // 1) QKV projection + fused RoPE epilogue -> Qf, Kf, Vf [B,H,L,HD]
    mma_gemm_qkv<<<dim3(NQKV / GBN, MROWS / GBM), 256, GEMM_SMEM>>>(
        xf, wq, rope_cos, rope_sin, Qf, Kf, Vf);

    // 2) flash attention (all single fp16) -> attf
    flash_attn<<<dim3(LL / 128, BB * HH), 256, ATT_SMEM>>>(
        Qf, Kf, Vf, attf);

    // 3) output projection + bias
    mma_gemm_bias<<<dim3(DD / GBN, MROWS / GBM), 256, GEMM_SMEM>>>(
        attf, wo, b_out, out, DD, DD);
}

// round 16
// speedup vs baseline: 1.0746x; 1.0134x over previous
#include <cuda_runtime.h>
#include <cuda_fp16.h>
#include <cstdint>

// Problem constants
#define BB 2
#define LL 2048
#define DD 1024
#define HH 16
#define HD 64
#define NQKV 3072        // 3*H*HD
#define MROWS (BB*LL)    // 4096

// ---------------- scratch (device globals; no allocations allowed) -------
__device__ __half g_xf[MROWS * DD];               // x single fp16
__device__ __half g_wqkvT[NQKV * DD];             // [N][K] single
__device__ __half g_woutT[DD * DD];               // [N][K] single

// attention operands, fp16 single, [B,H,L,HD] (Q scaled by 0.125*log2e)
__device__ __half g_Qf[BB * HH * LL * HD];
__device__ __half g_Kf[BB * HH * LL * HD];
__device__ __half g_Vf[BB * HH * LL * HD];
__device__ __half g_attf[MROWS * DD];             // [B*L, 1024] single

// ==================== helpers =============================================
__device__ __forceinline__ uint32_t smem_u32(const void* p) {
    uint32_t a;
    asm("{ .reg .u64 t; cvta.to.shared.u64 t, %1; cvt.u32.u64 %0, t; }"
        : "=r"(a) : "l"(p));
    return a;
}

// pack two floats -> half2 reg (a in low half)
__device__ __forceinline__ uint32_t pack2h(float a, float b) {
    __half2 h = __floats2half2_rn(a, b);
    return *(uint32_t*)&h;
}

__device__ __forceinline__ void ldsm4(uint32_t* r, uint32_t addr) {
    asm volatile("ldmatrix.sync.aligned.m8n8.x4.shared.b16 {%0,%1,%2,%3}, [%4];"
                 : "=r"(r[0]), "=r"(r[1]), "=r"(r[2]), "=r"(r[3]) : "r"(addr));
}

__device__ __forceinline__ void ldsm4t(uint32_t* r, uint32_t addr) {
    asm volatile("ldmatrix.sync.aligned.m8n8.x4.trans.shared.b16 {%0,%1,%2,%3}, [%4];"
                 : "=r"(r[0]), "=r"(r[1]), "=r"(r[2]), "=r"(r[3]) : "r"(addr));
}

__device__ __forceinline__ void mma_f16(float* d, const uint32_t* a, uint32_t b0, uint32_t b1) {
    asm volatile(
        "mma.sync.aligned.m16n8k16.row.col.f32.f16.f16.f32 "
        "{%0,%1,%2,%3}, {%4,%5,%6,%7}, {%8,%9}, {%0,%1,%2,%3};"
        : "+f"(d[0]), "+f"(d[1]), "+f"(d[2]), "+f"(d[3])
        : "r"(a[0]), "r"(a[1]), "r"(a[2]), "r"(a[3]), "r"(b0), "r"(b1));
}

// cp.async with L1 caching (.ca)
__device__ __forceinline__ void cpa16(uint32_t dst, const void* src) {
    asm volatile("cp.async.ca.shared.global [%0], [%1], 16;" :: "r"(dst), "l"(src));
}
#define CP_COMMIT() asm volatile("cp.async.commit_group;" ::: "memory")
#define CP_WAIT0()  asm volatile("cp.async.wait_group 0;" ::: "memory")
#define CP_WAIT1()  asm volatile("cp.async.wait_group 1;" ::: "memory")

// fast exp2 on FMA pipe (x <= 0 expected; clamped at -120)
__device__ __forceinline__ float fexp2(float x) {
    x = fmaxf(x, -120.0f);
    float n = floorf(x);
    float f = x - n;
    float p = 1.5404226e-4f;
    p = fmaf(p, f, 1.3333558e-3f);
    p = fmaf(p, f, 9.6181291e-3f);
    p = fmaf(p, f, 5.5504109e-2f);
    p = fmaf(p, f, 2.4022651e-1f);
    p = fmaf(p, f, 6.9314718e-1f);
    p = fmaf(p, f, 1.0f);
    return __int_as_float(__float_as_int(p) + (((int)n) << 23));
}

// ==================== fused conversion kernel =============================
#define CONV_XBLKS  (MROWS * DD / 4 / 256)       // 4096
#define CONV_QBLKS  ((NQKV / 32) * (DD / 32))    // 3072
#define CONV_OBLKS  ((DD / 32) * (DD / 32))      // 1024

__global__ void conv_all(const float* __restrict__ x, __half* __restrict__ xf,
                         const float* __restrict__ Wq, __half* __restrict__ WqT,
                         const float* __restrict__ Wo, __half* __restrict__ WoT)
{
    const int bid = blockIdx.x;
    const int tid = threadIdx.x;

    if (bid < CONV_XBLKS) {
        const int i = bid * 256 + tid;
        float4 v = ((const float4*)x)[i];
        __half h[4];
        h[0] = __float2half_rn(v.x);
        h[1] = __float2half_rn(v.y);
        h[2] = __float2half_rn(v.z);
        h[3] = __float2half_rn(v.w);
        ((uint2*)xf)[i] = *(uint2*)h;
        return;
    }

    const float* W;
    __half* T;
    int nb, kb, Ndim;
    if (bid < CONV_XBLKS + CONV_QBLKS) {
        const int b2 = bid - CONV_XBLKS;
        W = Wq; T = WqT; Ndim = NQKV;
        nb = (b2 % (NQKV / 32)) * 32;
        kb = (b2 / (NQKV / 32)) * 32;
    } else {
        const int b3 = bid - CONV_XBLKS - CONV_QBLKS;
        W = Wo; T = WoT; Ndim = DD;
        nb = (b3 % (DD / 32)) * 32;
        kb = (b3 / (DD / 32)) * 32;
    }

    __shared__ float t[32][33];
    const int tx = tid & 31, ty = tid >> 5;
    #pragma unroll
    for (int i = 0; i < 4; i++)
        t[ty + i * 8][tx] = W[(size_t)(kb + ty + i * 8) * Ndim + nb + tx];
    __syncthreads();
    #pragma unroll
    for (int i = 0; i < 4; i++) {
        const float v = t[tx][ty + i * 8];
        T[(size_t)(nb + ty + i * 8) * DD + kb + tx] = __float2half_rn(v);
    }
}

// ====== GEMM: CTA 128x128, warp 32x64, K-chunk 32, 3-stage ring ==========
#define GBM 128
#define GBN 128
#define GBK 32
#define SROW 20                       // padded row stride (u32) = 80B
#define GOP  (GBM * SROW * 4)         // one operand buffer: 10240 B
#define GA   0                        // A (3 buffers)
#define GB   (3 * GOP)                // W (3 buffers)
#define GEMM_SMEM (6 * GOP)           // 61440 B

struct GemmCtx {
    uint32_t sb;
    int warpM, warpN, lane;
    int mBase, nBase;
};

__device__ __forceinline__ void gemm_mainloop(
    const GemmCtx& g, const __half* Afg, const __half* Bg,
    int K, int tid, float acc[2][8][4])
{
    const int row = tid >> 1;
    const int seg = tid & 1;
    const uint32_t so = (row * SROW + seg * 8) * 4;
    const int nchunks = K / GBK;
    const uint32_t lrow = g.lane & 15;
    const uint32_t lhi  = (g.lane >> 4) << 4;

    auto stage = [&](int c, int buf) {
        const int k0 = c * GBK;
        const size_t ga = (size_t)(g.mBase + row) * K + k0 + seg * 16;
        const size_t gb = (size_t)(g.nBase + row) * K + k0 + seg * 16;
        cpa16(g.sb + GA + buf * GOP + so,      Afg + ga);
        cpa16(g.sb + GA + buf * GOP + so + 16, Afg + ga + 8);
        cpa16(g.sb + GB + buf * GOP + so,      Bg  + gb);
        cpa16(g.sb + GB + buf * GOP + so + 16, Bg  + gb + 8);
    };

    stage(0, 0); CP_COMMIT();
    stage(1, 1); CP_COMMIT();

    for (int c = 0; c < nchunks; c++) {
        if (c + 1 < nchunks) { CP_WAIT1(); } else { CP_WAIT0(); }
        __syncthreads();

        const uint32_t bA = g.sb + GA + (c % 3) * GOP;
        const uint32_t bB = g.sb + GB + (c % 3) * GOP;

        #pragma unroll
        for (int ks = 0; ks < 2; ks++) {
            const uint32_t kboff = ks * 32 + lhi;
            uint32_t ah[2][4];
            uint32_t bf[4][4];
            #pragma unroll
            for (int mt = 0; mt < 2; mt++) {
                const uint32_t ro = (g.warpM * 32 + mt * 16 + lrow) * (SROW * 4) + kboff;
                ldsm4(ah[mt], bA + ro);
            }
            #pragma unroll
            for (int reg = 0; reg < 4; reg++) {
                const uint32_t ro = (g.warpN * 64 + reg * 16 + lrow) * (SROW * 4) + kboff;
                ldsm4(bf[reg], bB + ro);
            }
            #pragma unroll
            for (int reg = 0; reg < 4; reg++)
                #pragma unroll
                for (int mt = 0; mt < 2; mt++)
                    #pragma unroll
                    for (int t = 0; t < 2; t++)
                        mma_f16(acc[mt][reg * 2 + t], ah[mt], bf[reg][t], bf[reg][t + 2]);
        }

        if (c + 2 < nchunks) { stage(c + 2, (c + 2) % 3); CP_COMMIT(); }
    }
}

// ---- QKV GEMM with fused RoPE epilogue: Q/K/V single fp16 ---------------
__global__ __launch_bounds__(256, 2)
void mma_gemm_qkv(const __half* __restrict__ Afg, const __half* __restrict__ Bg,
                  const float* __restrict__ cosT, const float* __restrict__ sinT,
                  __half* __restrict__ Qf, __half* __restrict__ Kf,
                  __half* __restrict__ Vf)
{
    extern __shared__ char gsm[];
    const int tid = threadIdx.x;
    GemmCtx g;
    g.sb = smem_u32(gsm);
    g.lane = tid & 31;
    const int wid = tid >> 5;
    g.warpM = wid & 3;          // 4 warps in M (32 rows each)
    g.warpN = wid >> 2;         // 2 warps in N (64 cols each)
    g.mBase = blockIdx.y * GBM;
    g.nBase = blockIdx.x * GBN;

    float acc[2][8][4];
    #pragma unroll
    for (int a = 0; a < 2; a++)
        #pragma unroll
        for (int b = 0; b < 8; b++)
            #pragma unroll
            for (int c2 = 0; c2 < 4; c2++) acc[a][b][c2] = 0.f;

    gemm_mainloop(g, Afg, Bg, DD, tid, acc);

    // ---- fused epilogue: RoPE (Q,K); all single fp16 ----
    const int qrow = g.lane >> 2;
    const int qcol = (g.lane & 3) * 2;
    const float qscale = 0.125f * 1.4426950408889634f;  // HD^-0.5 * log2(e)

    const int colbase = g.nBase + g.warpN * 64;
    const int h3  = colbase >> 6;
    const int sec = h3 >> 4;                // 0=Q 1=K 2=V
    const int h   = h3 & 15;

    #pragma unroll
    for (int mt = 0; mt < 2; mt++) {
        const int r0 = g.mBase + g.warpM * 32 + mt * 16 + qrow;
        const int b  = r0 >> 11;          // /LL
        const int l0 = r0 & (LL - 1);
        const int l1 = l0 + 8;
        const size_t o0 = (((size_t)(b * HH + h) * LL) + l0) * HD;
        const size_t o1 = o0 + 8 * HD;
        #pragma unroll
        for (int n8 = 0; n8 < 4; n8++) {
            const int d = n8 * 8 + qcol;            // 0..31 within head

            const float a0 = acc[mt][n8][0], a1 = acc[mt][n8][1];
            const float a2 = acc[mt][n8][2], a3 = acc[mt][n8][3];
            const float b0 = acc[mt][n8 + 4][0], b1 = acc[mt][n8 + 4][1];
            const float b2 = acc[mt][n8 + 4][2], b3 = acc[mt][n8 + 4][3];

            if (sec == 2) {
                *(uint32_t*)(Vf + o0 + d)      = pack2h(a0, a1);
                *(uint32_t*)(Vf + o1 + d)      = pack2h(a2, a3);
                *(uint32_t*)(Vf + o0 + d + 32) = pack2h(b0, b1);
                *(uint32_t*)(Vf + o1 + d + 32) = pack2h(b2, b3);
            } else {
                const float2 cl0 = *(const float2*)(cosT + l0 * HD + d);
                const float2 ch0 = *(const float2*)(cosT + l0 * HD + d + 32);
                const float2 sl0 = *(const float2*)(sinT + l0 * HD + d);
                const float2 sh0 = *(const float2*)(sinT + l0 * HD + d + 32);
                const float2 cl1 = *(const float2*)(cosT + l1 * HD + d);
                const float2 ch1 = *(const float2*)(cosT + l1 * HD + d + 32);
                const float2 sl1 = *(const float2*)(sinT + l1 * HD + d);
                const float2 sh1 = *(const float2*)(sinT + l1 * HD + d + 32);

                // row l0
                float rl0 = a0 * cl0.x - b0 * sl0.x;
                float rl1 = a1 * cl0.y - b1 * sl0.y;
                float rh0 = b0 * ch0.x + a0 * sh0.x;
                float rh1 = b1 * ch0.y + a1 * sh0.y;
                // row l1
                float ql0 = a2 * cl1.x - b2 * sl1.x;
                float ql1 = a3 * cl1.y - b3 * sl1.y;
                float qh0 = b2 * ch1.x + a2 * sh1.x;
                float qh1 = b3 * ch1.y + a3 * sh1.y;

                if (sec == 0) {
                    *(uint32_t*)(Qf + o0 + d)      = pack2h(rl0 * qscale, rl1 * qscale);
                    *(uint32_t*)(Qf + o0 + d + 32) = pack2h(rh0 * qscale, rh1 * qscale);
                    *(uint32_t*)(Qf + o1 + d)      = pack2h(ql0 * qscale, ql1 * qscale);
                    *(uint32_t*)(Qf + o1 + d + 32) = pack2h(qh0 * qscale, qh1 * qscale);
                } else {
                    *(uint32_t*)(Kf + o0 + d)      = pack2h(rl0, rl1);
                    *(uint32_t*)(Kf + o0 + d + 32) = pack2h(rh0, rh1);
                    *(uint32_t*)(Kf + o1 + d)      = pack2h(ql0, ql1);
                    *(uint32_t*)(Kf + o1 + d + 32) = pack2h(qh0, qh1);
                }
            }
        }
    }
}

// ---- output projection GEMM (+bias), fp32 out ----------------------------
__global__ __launch_bounds__(256, 2)
void mma_gemm_bias(const __half* __restrict__ Afg, const __half* __restrict__ Bg,
                   const float* __restrict__ bias, float* __restrict__ C,
                   int Ntot, int K)
{
    extern __shared__ char gsm[];
    const int tid = threadIdx.x;
    GemmCtx g;
    g.sb = smem_u32(gsm);
    g.lane = tid & 31;
    const int wid = tid >> 5;
    g.warpM = wid & 3;
    g.warpN = wid >> 2;
    g.mBase = blockIdx.y * GBM;
    g.nBase = blockIdx.x * GBN;

    float acc[2][8][4];
    #pragma unroll
    for (int a = 0; a < 2; a++)
        #pragma unroll
        for (int b = 0; b < 8; b++)
            #pragma unroll
            for (int c2 = 0; c2 < 4; c2++) acc[a][b][c2] = 0.f;

    gemm_mainloop(g, Afg, Bg, K, tid, acc);

    const int qrow = g.lane >> 2;
    const int qcol = (g.lane & 3) * 2;
    #pragma unroll
    for (int mt = 0; mt < 2; mt++) {
        const int m0 = g.mBase + g.warpM * 32 + mt * 16 + qrow;
        #pragma unroll
        for (int n8 = 0; n8 < 8; n8++) {
            const int col = g.nBase + g.warpN * 64 + n8 * 8 + qcol;
            float2 v0, v1;
            v0.x = acc[mt][n8][0]; v0.y = acc[mt][n8][1];
            v1.x = acc[mt][n8][2]; v1.y = acc[mt][n8][3];
            const float b0 = bias[col], b1 = bias[col + 1];
            v0.x += b0; v0.y += b1;
            v1.x += b0; v1.y += b1;
            *(float2*)&C[(size_t)m0 * Ntot + col] = v0;
            *(float2*)&C[(size_t)(m0 + 8) * Ntot + col] = v1;
        }
    }
}

// ------ flash attention: TK=128 tiles, 2-buffer ring, 1 barrier/tile ------
#define RSTRIDE 144               // padded smem row (72 fp16)
#define ASQ  0                    // Q region: 128 * 144 = 18432
#define KVB  18432                // KV ring base (2 buffers)
#define KVSZ 36864                // one KV buffer: K 128 rows + V 128 rows
#define KOFF_V 18432              // V region within buffer
#define ATT_SMEM (KVB + 2 * KVSZ) // 92160

__global__ __launch_bounds__(256, 2)
void flash_attn(const __half* __restrict__ Qfg,
                const __half* __restrict__ Kfg, const __half* __restrict__ Vfg,
                __half* __restrict__ Of)
{
    extern __shared__ char smem[];
    const uint32_t sb = smem_u32(smem);
    const int tid = threadIdx.x, wid = tid >> 5, lane = tid & 31;
    const int qt = (LL / 128 - 1) - blockIdx.x;     // big tiles first
    const int bh = blockIdx.y;
    const int b = bh >> 4, h = bh & 15;
    const int q0 = qt * 128;
    const size_t base = (size_t)bh * LL * HD;

    const int ntiles = q0 / 128 + 1;                // 128-key tiles

    auto stage_kv = [&](int t, int buf) {
        const int k0 = t * 128;
        const uint32_t bo = KVB + buf * KVSZ;
        #pragma unroll
        for (int j = 0; j < 4; j++) {
            const int item = j * 256 + tid;          // 0..1023
            const int row = item >> 3, seg = item & 7;
            const size_t g = base + (size_t)(k0 + row) * HD + seg * 8;
            const uint32_t so = bo + row * RSTRIDE + seg * 16;
            cpa16(sb + so,           Kfg + g);
            cpa16(sb + so + KOFF_V,  Vfg + g);
        }
    };

    // ---- initial: Q tile + KV tile 0 in one group ----
    {
        const int row = tid >> 1, seg = tid & 1;
        const size_t g = base + (size_t)(q0 + row) * HD + seg * 32;
        const uint32_t dq = sb + ASQ + row * RSTRIDE + seg * 64;
        #pragma unroll
        for (int i = 0; i < 4; i++)
            cpa16(dq + i * 16, Qfg + g + i * 8);
    }
    stage_kv(0, 0);
    CP_COMMIT();

    float acc_o[8][4];
    #pragma unroll
    for (int j = 0; j < 8; j++)
        #pragma unroll
        for (int e = 0; e < 4; e++) acc_o[j][e] = 0.f;
    float m0 = -1e30f, m1 = -1e30f, l0 = 0.f, l1 = 0.f;
    uint32_t qf[4][4];

    const int qmin = q0 + wid * 16;
    const int r_lo = qmin + (lane >> 2);

    for (int t = 0; t < ntiles; t++) {
        CP_WAIT0();
        __syncthreads();

        if (t == 0) {
            // one-time Q fragment load (region never overwritten)
            const uint32_t ro = (wid * 16 + (lane & 15)) * RSTRIDE + ((lane >> 4) << 4);
            #pragma unroll
            for (int ks = 0; ks < 4; ks++)
                ldsm4(qf[ks], sb + ASQ + ro + ks * 32);
        }

        // prefetch next 128-key tile into the buffer freed at iter t-1
        if (t + 1 < ntiles) { stage_kv(t + 1, (t + 1) & 1); CP_COMMIT(); }

        const uint32_t kb = sb + KVB + (t & 1) * KVSZ;

        #pragma unroll
        for (int sub = 0; sub < 2; sub++) {
            const int k0 = t * 128 + sub * 64;
            if (k0 > qmin + 15) break;               // masked for this warp
            const uint32_t kbs = kb + sub * 64 * RSTRIDE;

            // ---- S = Q·Kᵀ ----
            float s[8][4];
            #pragma unroll
            for (int j = 0; j < 8; j++)
                #pragma unroll
                for (int e = 0; e < 4; e++) s[j][e] = 0.f;

            #pragma unroll
            for (int ks = 0; ks < 4; ks++) {
                #pragma unroll
                for (int kp = 0; kp < 2; kp++) {
                    uint32_t kf[2][4];
                    #pragma unroll
                    for (int i = 0; i < 2; i++) {
                        const int np = kp * 2 + i;
                        const uint32_t ro = (np * 16 + (lane & 15)) * RSTRIDE +
                                            ((lane >> 4) << 4) + ks * 32;
                        ldsm4(kf[i], kbs + ro);
                    }
                    #pragma unroll
                    for (int i = 0; i < 2; i++) {
                        const int np = kp * 2 + i;
                        mma_f16(s[2 * np],     qf[ks], kf[i][0], kf[i][2]);
                        mma_f16(s[2 * np + 1], qf[ks], kf[i][1], kf[i][3]);
                    }
                }
            }

            // ---- causal mask ----
            if (k0 + 63 > qmin) {
                #pragma unroll
                for (int j = 0; j < 8; j++) {
                    const int key = k0 + j * 8 + (lane & 3) * 2;
                    if (key     > r_lo)     s[j][0] = -1e30f;
                    if (key + 1 > r_lo)     s[j][1] = -1e30f;
                    if (key     > r_lo + 8) s[j][2] = -1e30f;
                    if (key + 1 > r_lo + 8) s[j][3] = -1e30f;
                }
            }

            // ---- online softmax (log2 domain) ----
            float rm0 = -1e30f, rm1 = -1e30f;
            #pragma unroll
            for (int j = 0; j < 8; j++) {
                rm0 = fmaxf(rm0, fmaxf(s[j][0], s[j][1]));
                rm1 = fmaxf(rm1, fmaxf(s[j][2], s[j][3]));
            }
            rm0 = fmaxf(rm0, __shfl_xor_sync(0xffffffff, rm0, 1));
            rm0 = fmaxf(rm0, __shfl_xor_sync(0xffffffff, rm0, 2));
            rm1 = fmaxf(rm1, __shfl_xor_sync(0xffffffff, rm1, 1));
            rm1 = fmaxf(rm1, __shfl_xor_sync(0xffffffff, rm1, 2));

            // skip rescale when no lane's running max changed (exact: c==1)
            const bool grow = (rm0 > m0) || (rm1 > m1);
            if (__any_sync(0xffffffff, grow)) {
                const float mn0 = fmaxf(m0, rm0), mn1 = fmaxf(m1, rm1);
                const float c0 = fexp2(m0 - mn0), c1 = fexp2(m1 - mn1);
                m0 = mn0; m1 = mn1;
                l0 *= c0; l1 *= c1;
                #pragma unroll
                for (int j = 0; j < 8; j++) {
                    acc_o[j][0] *= c0; acc_o[j][1] *= c0;
                    acc_o[j][2] *= c1; acc_o[j][3] *= c1;
                }
            }

            #pragma unroll
            for (int j = 0; j < 8; j++) {
                s[j][0] = fexp2(s[j][0] - m0);
                s[j][1] = fexp2(s[j][1] - m0);
                s[j][2] = fexp2(s[j][2] - m1);
                s[j][3] = fexp2(s[j][3] - m1);
                l0 += s[j][0] + s[j][1];
                l1 += s[j][2] + s[j][3];
            }

            // ---- O += P·V (P single fp16) ----
            #pragma unroll
            for (int ks = 0; ks < 4; ks++) {
                uint32_t pf[4];
                const int j0 = 2 * ks, j1 = 2 * ks + 1;
                pf[0] = pack2h(s[j0][0], s[j0][1]);
                pf[1] = pack2h(s[j0][2], s[j0][3]);
                pf[2] = pack2h(s[j1][0], s[j1][1]);
                pf[3] = pack2h(s[j1][2], s[j1][3]);

                #pragma unroll
                for (int vp = 0; vp < 2; vp++) {
                    uint32_t vf[2][4];
                    #pragma unroll
                    for (int i = 0; i < 2; i++) {
                        const int np = vp * 2 + i;
                        const int g = lane >> 3;
                        const uint32_t vrow = sub * 64 + ks * 16 + (g & 1) * 8 + (lane & 7);
                        const uint32_t ro = vrow * RSTRIDE + np * 32 + (g >> 1) * 16;
                        ldsm4t(vf[i], kb + KOFF_V + ro);
                    }
                    #pragma unroll
                    for (int i = 0; i < 2; i++) {
                        const int np = vp * 2 + i;
                        mma_f16(acc_o[2 * np],     pf, vf[i][0], vf[i][1]);
                        mma_f16(acc_o[2 * np + 1], pf, vf[i][2], vf[i][3]);
                    }
                }
            }
        }
    }

    // ---- epilogue: normalize, write single fp16 [B*L, 1024] ----
    l0 += __shfl_xor_sync(0xffffffff, l0, 1);
    l0 += __shfl_xor_sync(0xffffffff, l0, 2);
    l1 += __shfl_xor_sync(0xffffffff, l1, 1);
    l1 += __shfl_xor_sync(0xffffffff, l1, 2);
    const float inv0 = 1.0f / l0, inv1 = 1.0f / l1;

    const size_t row0 = (size_t)(b * LL + q0 + wid * 16 + (lane >> 2));
    const size_t row1 = row0 + 8;
    const int colbase = h * HD + (lane & 3) * 2;
    #pragma unroll
    for (int j = 0; j < 8; j++) {
        const int col = colbase + j * 8;
        *(uint32_t*)(Of + row0 * DD + col) = pack2h(acc_o[j][0] * inv0, acc_o[j][1] * inv0);
        *(uint32_t*)(Of + row1 * DD + col) = pack2h(acc_o[j][2] * inv1, acc_o[j][3] * inv1);
    }
}

// -------------------------------------------------------------------------
extern "C" void kernel_launch(void* const* d_in, const int* in_sizes, int n_in,
                              void* d_out, int out_size)
{
    const float* x        = (const float*)d_in[0];
    const float* rope_cos = (const float*)d_in[1];
    const float* rope_sin = (const float*)d_in[2];
    const float* W_qkv    = (const float*)d_in[3];
    const float* W_out    = (const float*)d_in[4];
    const float* b_out    = (const float*)d_in[5];
    float* out = (float*)d_out;

    __half *xf, *wq, *wo, *attf, *Qf, *Kf, *Vf;
    cudaGetSymbolAddress((void**)&xf,   g_xf);
    cudaGetSymbolAddress((void**)&wq,   g_wqkvT);
    cudaGetSymbolAddress((void**)&wo,   g_woutT);
    cudaGetSymbolAddress((void**)&attf, g_attf);
    cudaGetSymbolAddress((void**)&Qf,   g_Qf);
    cudaGetSymbolAddress((void**)&Kf,   g_Kf);
    cudaGetSymbolAddress((void**)&Vf,   g_Vf);

    cudaFuncSetAttribute(flash_attn,    cudaFuncAttributeMaxDynamicSharedMemorySize, ATT_SMEM);
    cudaFuncSetAttribute(mma_gemm_qkv,  cudaFuncAttributeMaxDynamicSharedMemorySize, GEMM_SMEM);
    cudaFuncSetAttribute(mma_gemm_bias, cudaFuncAttributeMaxDynamicSharedMemorySize, GEMM_SMEM);

    // 0) fused operand conversion (x, W_qkvT, W_outT) in ONE launch
    conv_all<<<CONV_XBLKS + CONV_QBLKS + CONV_OBLKS, 256>>>(
        x, xf, W_qkv, wq, W_out, wo);

    // 1) QKV projection + fused RoPE epilogue -> Qf, Kf, Vf [B,H,L,HD]
    mma_gemm_qkv<<<dim3(NQKV / GBN, MROWS / GBM), 256, GEMM_SMEM>>>(
        xf, wq, rope_cos, rope_sin, Qf, Kf, Vf);

    // 2) flash attention (all single fp16, TK=128) -> attf
    flash_attn<<<dim3(LL / 128, BB * HH), 256, ATT_SMEM>>>(
        Qf, Kf, Vf, attf);

    // 3) output projection + bias
    mma_gemm_bias<<<dim3(DD / GBN, MROWS / GBM), 256, GEMM_SMEM>>>(
        attf, wo, b_out, out, DD, DD);
}

// round 17
// speedup vs baseline: 1.1018x; 1.0253x over previous
#include <cuda_runtime.h>
#include <cuda_fp16.h>
#include <cstdint>

// Problem constants
#define BB 2
#define LL 2048
#define DD 1024
#define HH 16
#define HD 64
#define NQKV 3072        // 3*H*HD
#define MROWS (BB*LL)    // 4096

// ---------------- scratch (device globals; no allocations allowed) -------
__device__ __half g_xf[MROWS * DD];               // x single fp16
__device__ __half g_wqkvT[NQKV * DD];             // [N][K] single
__device__ __half g_woutT[DD * DD];               // [N][K] single

// attention operands, fp16 single, [B,H,L,HD] (Q scaled by 0.125*log2e)
__device__ __half g_Qf[BB * HH * LL * HD];
__device__ __half g_Kf[BB * HH * LL * HD];
__device__ __half g_Vf[BB * HH * LL * HD];
__device__ __half g_attf[MROWS * DD];             // [B*L, 1024] single

// ==================== helpers =============================================
__device__ __forceinline__ uint32_t smem_u32(const void* p) {
    uint32_t a;
    asm("{ .reg .u64 t; cvta.to.shared.u64 t, %1; cvt.u32.u64 %0, t; }"
        : "=r"(a) : "l"(p));
    return a;
}

// pack two floats -> half2 reg (a in low half)
__device__ __forceinline__ uint32_t pack2h(float a, float b) {
    __half2 h = __floats2half2_rn(a, b);
    return *(uint32_t*)&h;
}

__device__ __forceinline__ void ldsm4(uint32_t* r, uint32_t addr) {
    asm volatile("ldmatrix.sync.aligned.m8n8.x4.shared.b16 {%0,%1,%2,%3}, [%4];"
                 : "=r"(r[0]), "=r"(r[1]), "=r"(r[2]), "=r"(r[3]) : "r"(addr));
}

__device__ __forceinline__ void ldsm4t(uint32_t* r, uint32_t addr) {
    asm volatile("ldmatrix.sync.aligned.m8n8.x4.trans.shared.b16 {%0,%1,%2,%3}, [%4];"
                 : "=r"(r[0]), "=r"(r[1]), "=r"(r[2]), "=r"(r[3]) : "r"(addr));
}

__device__ __forceinline__ void mma_f16(float* d, const uint32_t* a, uint32_t b0, uint32_t b1) {
    asm volatile(
        "mma.sync.aligned.m16n8k16.row.col.f32.f16.f16.f32 "
        "{%0,%1,%2,%3}, {%4,%5,%6,%7}, {%8,%9}, {%0,%1,%2,%3};"
        : "+f"(d[0]), "+f"(d[1]), "+f"(d[2]), "+f"(d[3])
        : "r"(a[0]), "r"(a[1]), "r"(a[2]), "r"(a[3]), "r"(b0), "r"(b1));
}

// cp.async with L1 caching (.ca)
__device__ __forceinline__ void cpa16(uint32_t dst, const void* src) {
    asm volatile("cp.async.ca.shared.global [%0], [%1], 16;" :: "r"(dst), "l"(src));
}
#define CP_COMMIT() asm volatile("cp.async.commit_group;" ::: "memory")
#define CP_WAIT0()  asm volatile("cp.async.wait_group 0;" ::: "memory")
#define CP_WAIT1()  asm volatile("cp.async.wait_group 1;" ::: "memory")

// fast exp2 on FMA pipe (x <= 0 expected; clamped at -120) — scalar (rare path)
__device__ __forceinline__ float fexp2(float x) {
    x = fmaxf(x, -120.0f);
    float n = floorf(x);
    float f = x - n;
    float p = 1.5404226e-4f;
    p = fmaf(p, f, 1.3333558e-3f);
    p = fmaf(p, f, 9.6181291e-3f);
    p = fmaf(p, f, 5.5504109e-2f);
    p = fmaf(p, f, 2.4022651e-1f);
    p = fmaf(p, f, 6.9314718e-1f);
    p = fmaf(p, f, 1.0f);
    return __int_as_float(__float_as_int(p) + (((int)n) << 23));
}

// ---- packed f32x2 helpers (sm_103a) ----
__device__ __forceinline__ uint64_t pkf2(float lo, float hi) {
    uint64_t r;
    asm("mov.b64 %0, {%1, %2};" : "=l"(r) : "f"(lo), "f"(hi));
    return r;
}
__device__ __forceinline__ void upkf2(uint64_t v, float& lo, float& hi) {
    asm("mov.b64 {%0, %1}, %2;" : "=f"(lo), "=f"(hi) : "l"(v));
}

// packed exp2 of two values (expected <= 0), clamped at -126.
// magic-constant round-to-nearest: n in mantissa bits, f in [-0.5, 0.5].
__device__ __forceinline__ uint64_t fexp2x2(float a, float b) {
    a = fmaxf(a, -126.0f);
    b = fmaxf(b, -126.0f);
    const uint64_t MAG  = pkf2(12582912.0f, 12582912.0f);    // 1.5*2^23
    const uint64_t NMAG = pkf2(-12582912.0f, -12582912.0f);
    const uint64_t NONE = pkf2(-1.0f, -1.0f);
    const uint64_t C5 = pkf2(1.3333558e-3f, 1.3333558e-3f);
    const uint64_t C4 = pkf2(9.6181291e-3f, 9.6181291e-3f);
    const uint64_t C3 = pkf2(5.5504109e-2f, 5.5504109e-2f);
    const uint64_t C2 = pkf2(2.4022651e-1f, 2.4022651e-1f);
    const uint64_t C1 = pkf2(6.9314718e-1f, 6.9314718e-1f);
    const uint64_t C0 = pkf2(1.0f, 1.0f);
    uint64_t x = pkf2(a, b), z, nf, f, p;
    asm("add.rn.f32x2 %0, %1, %2;" : "=l"(z)  : "l"(x),  "l"(MAG));
    asm("add.rn.f32x2 %0, %1, %2;" : "=l"(nf) : "l"(z),  "l"(NMAG));
    asm("fma.rn.f32x2 %0, %1, %2, %3;" : "=l"(f) : "l"(nf), "l"(NONE), "l"(x));
    asm("fma.rn.f32x2 %0, %1, %2, %3;" : "=l"(p) : "l"(C5), "l"(f), "l"(C4));
    asm("fma.rn.f32x2 %0, %1, %2, %3;" : "=l"(p) : "l"(p),  "l"(f), "l"(C3));
    asm("fma.rn.f32x2 %0, %1, %2, %3;" : "=l"(p) : "l"(p),  "l"(f), "l"(C2));
    asm("fma.rn.f32x2 %0, %1, %2, %3;" : "=l"(p) : "l"(p),  "l"(f), "l"(C1));
    asm("fma.rn.f32x2 %0, %1, %2, %3;" : "=l"(p) : "l"(p),  "l"(f), "l"(C0));
    // scale each component by 2^n: resbits = pbits + (zbits << 23)
    const uint32_t z0 = (uint32_t)z, z1 = (uint32_t)(z >> 32);
    const uint32_t p0 = (uint32_t)p, p1 = (uint32_t)(p >> 32);
    const uint32_t r0 = p0 + (z0 << 23);
    const uint32_t r1 = p1 + (z1 << 23);
    return ((uint64_t)r1 << 32) | (uint64_t)r0;
}

// ==================== fused conversion kernel =============================
#define CONV_XBLKS  (MROWS * DD / 4 / 256)       // 4096
#define CONV_QBLKS  ((NQKV / 32) * (DD / 32))    // 3072
#define CONV_OBLKS  ((DD / 32) * (DD / 32))      // 1024

__global__ void conv_all(const float* __restrict__ x, __half* __restrict__ xf,
                         const float* __restrict__ Wq, __half* __restrict__ WqT,
                         const float* __restrict__ Wo, __half* __restrict__ WoT)
{
    const int bid = blockIdx.x;
    const int tid = threadIdx.x;

    if (bid < CONV_XBLKS) {
        const int i = bid * 256 + tid;
        float4 v = ((const float4*)x)[i];
        __half h[4];
        h[0] = __float2half_rn(v.x);
        h[1] = __float2half_rn(v.y);
        h[2] = __float2half_rn(v.z);
        h[3] = __float2half_rn(v.w);
        ((uint2*)xf)[i] = *(uint2*)h;
        return;
    }

    const float* W;
    __half* T;
    int nb, kb, Ndim;
    if (bid < CONV_XBLKS + CONV_QBLKS) {
        const int b2 = bid - CONV_XBLKS;
        W = Wq; T = WqT; Ndim = NQKV;
        nb = (b2 % (NQKV / 32)) * 32;
        kb = (b2 / (NQKV / 32)) * 32;
    } else {
        const int b3 = bid - CONV_XBLKS - CONV_QBLKS;
        W = Wo; T = WoT; Ndim = DD;
        nb = (b3 % (DD / 32)) * 32;
        kb = (b3 / (DD / 32)) * 32;
    }

    __shared__ float t[32][33];
    const int tx = tid & 31, ty = tid >> 5;
    #pragma unroll
    for (int i = 0; i < 4; i++)
        t[ty + i * 8][tx] = W[(size_t)(kb + ty + i * 8) * Ndim + nb + tx];
    __syncthreads();
    #pragma unroll
    for (int i = 0; i < 4; i++) {
        const float v = t[tx][ty + i * 8];
        T[(size_t)(nb + ty + i * 8) * DD + kb + tx] = __float2half_rn(v);
    }
}

// ====== GEMM: CTA 128x128, warp 32x64, K-chunk 32, 3-stage ring ==========
#define GBM 128
#define GBN 128
#define GBK 32
#define SROW 20                       // padded row stride (u32) = 80B
#define GOP  (GBM * SROW * 4)         // one operand buffer: 10240 B
#define GA   0                        // A (3 buffers)
#define GB   (3 * GOP)                // W (3 buffers)
#define GEMM_SMEM (6 * GOP)           // 61440 B

struct GemmCtx {
    uint32_t sb;
    int warpM, warpN, lane;
    int mBase, nBase;
};

__device__ __forceinline__ void gemm_mainloop(
    const GemmCtx& g, const __half* Afg, const __half* Bg,
    int K, int tid, float acc[2][8][4])
{
    const int row = tid >> 1;
    const int seg = tid & 1;
    const uint32_t so = (row * SROW + seg * 8) * 4;
    const int nchunks = K / GBK;
    const uint32_t lrow = g.lane & 15;
    const uint32_t lhi  = (g.lane >> 4) << 4;

    auto stage = [&](int c, int buf) {
        const int k0 = c * GBK;
        const size_t ga = (size_t)(g.mBase + row) * K + k0 + seg * 16;
        const size_t gb = (size_t)(g.nBase + row) * K + k0 + seg * 16;
        cpa16(g.sb + GA + buf * GOP + so,      Afg + ga);
        cpa16(g.sb + GA + buf * GOP + so + 16, Afg + ga + 8);
        cpa16(g.sb + GB + buf * GOP + so,      Bg  + gb);
        cpa16(g.sb + GB + buf * GOP + so + 16, Bg  + gb + 8);
    };

    stage(0, 0); CP_COMMIT();
    stage(1, 1); CP_COMMIT();

    for (int c = 0; c < nchunks; c++) {
        if (c + 1 < nchunks) { CP_WAIT1(); } else { CP_WAIT0(); }
        __syncthreads();

        const uint32_t bA = g.sb + GA + (c % 3) * GOP;
        const uint32_t bB = g.sb + GB + (c % 3) * GOP;

        #pragma unroll
        for (int ks = 0; ks < 2; ks++) {
            const uint32_t kboff = ks * 32 + lhi;
            uint32_t ah[2][4];
            uint32_t bf[4][4];
            #pragma unroll
            for (int mt = 0; mt < 2; mt++) {
                const uint32_t ro = (g.warpM * 32 + mt * 16 + lrow) * (SROW * 4) + kboff;
                ldsm4(ah[mt], bA + ro);
            }
            #pragma unroll
            for (int reg = 0; reg < 4; reg++) {
                const uint32_t ro = (g.warpN * 64 + reg * 16 + lrow) * (SROW * 4) + kboff;
                ldsm4(bf[reg], bB + ro);
            }
            #pragma unroll
            for (int reg = 0; reg < 4; reg++)
                #pragma unroll
                for (int mt = 0; mt < 2; mt++)
                    #pragma unroll
                    for (int t = 0; t < 2; t++)
                        mma_f16(acc[mt][reg * 2 + t], ah[mt], bf[reg][t], bf[reg][t + 2]);
        }

        if (c + 2 < nchunks) { stage(c + 2, (c + 2) % 3); CP_COMMIT(); }
    }
}

// ---- QKV GEMM with fused RoPE epilogue: Q/K/V single fp16 ---------------
__global__ __launch_bounds__(256, 2)
void mma_gemm_qkv(const __half* __restrict__ Afg, const __half* __restrict__ Bg,
                  const float* __restrict__ cosT, const float* __restrict__ sinT,
                  __half* __restrict__ Qf, __half* __restrict__ Kf,
                  __half* __restrict__ Vf)
{
    extern __shared__ char gsm[];
    const int tid = threadIdx.x;
    GemmCtx g;
    g.sb = smem_u32(gsm);
    g.lane = tid & 31;
    const int wid = tid >> 5;
    g.warpM = wid & 3;          // 4 warps in M (32 rows each)
    g.warpN = wid >> 2;         // 2 warps in N (64 cols each)
    g.mBase = blockIdx.y * GBM;
    g.nBase = blockIdx.x * GBN;

    float acc[2][8][4];
    #pragma unroll
    for (int a = 0; a < 2; a++)
        #pragma unroll
        for (int b = 0; b < 8; b++)
            #pragma unroll
            for (int c2 = 0; c2 < 4; c2++) acc[a][b][c2] = 0.f;

    gemm_mainloop(g, Afg, Bg, DD, tid, acc);

    // ---- fused epilogue: RoPE (Q,K); all single fp16 ----
    const int qrow = g.lane >> 2;
    const int qcol = (g.lane & 3) * 2;
    const float qscale = 0.125f * 1.4426950408889634f;  // HD^-0.5 * log2(e)

    const int colbase = g.nBase + g.warpN * 64;
    const int h3  = colbase >> 6;
    const int sec = h3 >> 4;                // 0=Q 1=K 2=V
    const int h   = h3 & 15;

    #pragma unroll
    for (int mt = 0; mt < 2; mt++) {
        const int r0 = g.mBase + g.warpM * 32 + mt * 16 + qrow;
        const int b  = r0 >> 11;          // /LL
        const int l0 = r0 & (LL - 1);
        const int l1 = l0 + 8;
        const size_t o0 = (((size_t)(b * HH + h) * LL) + l0) * HD;
        const size_t o1 = o0 + 8 * HD;
        #pragma unroll
        for (int n8 = 0; n8 < 4; n8++) {
            const int d = n8 * 8 + qcol;            // 0..31 within head

            const float a0 = acc[mt][n8][0], a1 = acc[mt][n8][1];
            const float a2 = acc[mt][n8][2], a3 = acc[mt][n8][3];
            const float b0 = acc[mt][n8 + 4][0], b1 = acc[mt][n8 + 4][1];
            const float b2 = acc[mt][n8 + 4][2], b3 = acc[mt][n8 + 4][3];

            if (sec == 2) {
                *(uint32_t*)(Vf + o0 + d)      = pack2h(a0, a1);
                *(uint32_t*)(Vf + o1 + d)      = pack2h(a2, a3);
                *(uint32_t*)(Vf + o0 + d + 32) = pack2h(b0, b1);
                *(uint32_t*)(Vf + o1 + d + 32) = pack2h(b2, b3);
            } else {
                const float2 cl0 = *(const float2*)(cosT + l0 * HD + d);
                const float2 ch0 = *(const float2*)(cosT + l0 * HD + d + 32);
                const float2 sl0 = *(const float2*)(sinT + l0 * HD + d);
                const float2 sh0 = *(const float2*)(sinT + l0 * HD + d + 32);
                const float2 cl1 = *(const float2*)(cosT + l1 * HD + d);
                const float2 ch1 = *(const float2*)(cosT + l1 * HD + d + 32);
                const float2 sl1 = *(const float2*)(sinT + l1 * HD + d);
                const float2 sh1 = *(const float2*)(sinT + l1 * HD + d + 32);

                // row l0
                float rl0 = a0 * cl0.x - b0 * sl0.x;
                float rl1 = a1 * cl0.y - b1 * sl0.y;
                float rh0 = b0 * ch0.x + a0 * sh0.x;
                float rh1 = b1 * ch0.y + a1 * sh0.y;
                // row l1
                float ql0 = a2 * cl1.x - b2 * sl1.x;
                float ql1 = a3 * cl1.y - b3 * sl1.y;
                float qh0 = b2 * ch1.x + a2 * sh1.x;
                float qh1 = b3 * ch1.y + a3 * sh1.y;

                if (sec == 0) {
                    *(uint32_t*)(Qf + o0 + d)      = pack2h(rl0 * qscale, rl1 * qscale);
                    *(uint32_t*)(Qf + o0 + d + 32) = pack2h(rh0 * qscale, rh1 * qscale);
                    *(uint32_t*)(Qf + o1 + d)      = pack2h(ql0 * qscale, ql1 * qscale);
                    *(uint32_t*)(Qf + o1 + d + 32) = pack2h(qh0 * qscale, qh1 * qscale);
                } else {
                    *(uint32_t*)(Kf + o0 + d)      = pack2h(rl0, rl1);
                    *(uint32_t*)(Kf + o0 + d + 32) = pack2h(rh0, rh1);
                    *(uint32_t*)(Kf + o1 + d)      = pack2h(ql0, ql1);
                    *(uint32_t*)(Kf + o1 + d + 32) = pack2h(qh0, qh1);
                }
            }
        }
    }
}

// ---- output projection GEMM (+bias), fp32 out ----------------------------
__global__ __launch_bounds__(256, 2)
void mma_gemm_bias(const __half* __restrict__ Afg, const __half* __restrict__ Bg,
                   const float* __restrict__ bias, float* __restrict__ C,
                   int Ntot, int K)
{
    extern __shared__ char gsm[];
    const int tid = threadIdx.x;
    GemmCtx g;
    g.sb = smem_u32(gsm);
    g.lane = tid & 31;
    const int wid = tid >> 5;
    g.warpM = wid & 3;
    g.warpN = wid >> 2;
    g.mBase = blockIdx.y * GBM;
    g.nBase = blockIdx.x * GBN;

    float acc[2][8][4];
    #pragma unroll
    for (int a = 0; a < 2; a++)
        #pragma unroll
        for (int b = 0; b < 8; b++)
            #pragma unroll
            for (int c2 = 0; c2 < 4; c2++) acc[a][b][c2] = 0.f;

    gemm_mainloop(g, Afg, Bg, K, tid, acc);

    const int qrow = g.lane >> 2;
    const int qcol = (g.lane & 3) * 2;
    #pragma unroll
    for (int mt = 0; mt < 2; mt++) {
        const int m0 = g.mBase + g.warpM * 32 + mt * 16 + qrow;
        #pragma unroll
        for (int n8 = 0; n8 < 8; n8++) {
            const int col = g.nBase + g.warpN * 64 + n8 * 8 + qcol;
            float2 v0, v1;
            v0.x = acc[mt][n8][0]; v0.y = acc[mt][n8][1];
            v1.x = acc[mt][n8][2]; v1.y = acc[mt][n8][3];
            const float b0 = bias[col], b1 = bias[col + 1];
            v0.x += b0; v0.y += b1;
            v1.x += b0; v1.y += b1;
            *(float2*)&C[(size_t)m0 * Ntot + col] = v0;
            *(float2*)&C[(size_t)(m0 + 8) * Ntot + col] = v1;
        }
    }
}

// ------ flash attention: TK=128 tiles, 2-buffer ring, 1 barrier/tile ------
#define RSTRIDE 144               // padded smem row (72 fp16)
#define ASQ  0                    // Q region: 128 * 144 = 18432
#define KVB  18432                // KV ring base (2 buffers)
#define KVSZ 36864                // one KV buffer: K 128 rows + V 128 rows
#define KOFF_V 18432              // V region within buffer
#define ATT_SMEM (KVB + 2 * KVSZ) // 92160

__global__ __launch_bounds__(256, 2)
void flash_attn(const __half* __restrict__ Qfg,
                const __half* __restrict__ Kfg, const __half* __restrict__ Vfg,
                __half* __restrict__ Of)
{
    extern __shared__ char smem[];
    const uint32_t sb = smem_u32(smem);
    const int tid = threadIdx.x, wid = tid >> 5, lane = tid & 31;
    const int qt = (LL / 128 - 1) - blockIdx.x;     // big tiles first
    const int bh = blockIdx.y;
    const int b = bh >> 4, h = bh & 15;
    const int q0 = qt * 128;
    const size_t base = (size_t)bh * LL * HD;

    const int ntiles = q0 / 128 + 1;                // 128-key tiles

    auto stage_kv = [&](int t, int buf) {
        const int k0 = t * 128;
        const uint32_t bo = KVB + buf * KVSZ;
        #pragma unroll
        for (int j = 0; j < 4; j++) {
            const int item = j * 256 + tid;          // 0..1023
            const int row = item >> 3, seg = item & 7;
            const size_t g = base + (size_t)(k0 + row) * HD + seg * 8;
            const uint32_t so = bo + row * RSTRIDE + seg * 16;
            cpa16(sb + so,           Kfg + g);
            cpa16(sb + so + KOFF_V,  Vfg + g);
        }
    };

    // ---- initial: Q tile + KV tile 0 in one group ----
    {
        const int row = tid >> 1, seg = tid & 1;
        const size_t g = base + (size_t)(q0 + row) * HD + seg * 32;
        const uint32_t dq = sb + ASQ + row * RSTRIDE + seg * 64;
        #pragma unroll
        for (int i = 0; i < 4; i++)
            cpa16(dq + i * 16, Qfg + g + i * 8);
    }
    stage_kv(0, 0);
    CP_COMMIT();

    float acc_o[8][4];
    #pragma unroll
    for (int j = 0; j < 8; j++)
        #pragma unroll
        for (int e = 0; e < 4; e++) acc_o[j][e] = 0.f;
    float m0 = -1e30f, m1 = -1e30f, l0 = 0.f, l1 = 0.f;
    uint32_t qf[4][4];

    const int qmin = q0 + wid * 16;
    const int r_lo = qmin + (lane >> 2);

    for (int t = 0; t < ntiles; t++) {
        CP_WAIT0();
        __syncthreads();

        if (t == 0) {
            const uint32_t ro = (wid * 16 + (lane & 15)) * RSTRIDE + ((lane >> 4) << 4);
            #pragma unroll
            for (int ks = 0; ks < 4; ks++)
                ldsm4(qf[ks], sb + ASQ + ro + ks * 32);
        }

        if (t + 1 < ntiles) { stage_kv(t + 1, (t + 1) & 1); CP_COMMIT(); }

        const uint32_t kb = sb + KVB + (t & 1) * KVSZ;

        #pragma unroll
        for (int sub = 0; sub < 2; sub++) {
            const int k0 = t * 128 + sub * 64;
            if (k0 > qmin + 15) break;               // masked for this warp
            const uint32_t kbs = kb + sub * 64 * RSTRIDE;

            // ---- S = Q·Kᵀ ----
            float s[8][4];
            #pragma unroll
            for (int j = 0; j < 8; j++)
                #pragma unroll
                for (int e = 0; e < 4; e++) s[j][e] = 0.f;

            #pragma unroll
            for (int ks = 0; ks < 4; ks++) {
                #pragma unroll
                for (int kp = 0; kp < 2; kp++) {
                    uint32_t kf[2][4];
                    #pragma unroll
                    for (int i = 0; i < 2; i++) {
                        const int np = kp * 2 + i;
                        const uint32_t ro = (np * 16 + (lane & 15)) * RSTRIDE +
                                            ((lane >> 4) << 4) + ks * 32;
                        ldsm4(kf[i], kbs + ro);
                    }
                    #pragma unroll
                    for (int i = 0; i < 2; i++) {
                        const int np = kp * 2 + i;
                        mma_f16(s[2 * np],     qf[ks], kf[i][0], kf[i][2]);
                        mma_f16(s[2 * np + 1], qf[ks], kf[i][1], kf[i][3]);
                    }
                }
            }

            // ---- causal mask ----
            if (k0 + 63 > qmin) {
                #pragma unroll
                for (int j = 0; j < 8; j++) {
                    const int key = k0 + j * 8 + (lane & 3) * 2;
                    if (key     > r_lo)     s[j][0] = -1e30f;
                    if (key + 1 > r_lo)     s[j][1] = -1e30f;
                    if (key     > r_lo + 8) s[j][2] = -1e30f;
                    if (key + 1 > r_lo + 8) s[j][3] = -1e30f;
                }
            }

            // ---- online softmax (log2 domain) ----
            float rm0 = -1e30f, rm1 = -1e30f;
            #pragma unroll
            for (int j = 0; j < 8; j++) {
                rm0 = fmaxf(rm0, fmaxf(s[j][0], s[j][1]));
                rm1 = fmaxf(rm1, fmaxf(s[j][2], s[j][3]));
            }
            rm0 = fmaxf(rm0, __shfl_xor_sync(0xffffffff, rm0, 1));
            rm0 = fmaxf(rm0, __shfl_xor_sync(0xffffffff, rm0, 2));
            rm1 = fmaxf(rm1, __shfl_xor_sync(0xffffffff, rm1, 1));
            rm1 = fmaxf(rm1, __shfl_xor_sync(0xffffffff, rm1, 2));

            // skip rescale when no lane's running max changed (exact: c==1)
            const bool grow = (rm0 > m0) || (rm1 > m1);
            if (__any_sync(0xffffffff, grow)) {
                const float mn0 = fmaxf(m0, rm0), mn1 = fmaxf(m1, rm1);
                const float c0 = fexp2(m0 - mn0), c1 = fexp2(m1 - mn1);
                m0 = mn0; m1 = mn1;
                l0 *= c0; l1 *= c1;
                #pragma unroll
                for (int j = 0; j < 8; j++) {
                    acc_o[j][0] *= c0; acc_o[j][1] *= c0;
                    acc_o[j][2] *= c1; acc_o[j][3] *= c1;
                }
            }

            // ---- p = exp2(s - m) via packed f32x2; accumulate l packed ----
            uint64_t l0v = 0ull, l1v = 0ull;
            #pragma unroll
            for (int j = 0; j < 8; j++) {
                uint64_t p01 = fexp2x2(s[j][0] - m0, s[j][1] - m0);
                uint64_t p23 = fexp2x2(s[j][2] - m1, s[j][3] - m1);
                asm("add.rn.f32x2 %0, %1, %2;" : "=l"(l0v) : "l"(l0v), "l"(p01));
                asm("add.rn.f32x2 %0, %1, %2;" : "=l"(l1v) : "l"(l1v), "l"(p23));
                upkf2(p01, s[j][0], s[j][1]);
                upkf2(p23, s[j][2], s[j][3]);
            }
            {
                float t0, t1;
                upkf2(l0v, t0, t1); l0 += t0 + t1;
                upkf2(l1v, t0, t1); l1 += t0 + t1;
            }

            // ---- O += P·V (P single fp16) ----
            #pragma unroll
            for (int ks = 0; ks < 4; ks++) {
                uint32_t pf[4];
                const int j0 = 2 * ks, j1 = 2 * ks + 1;
                pf[0] = pack2h(s[j0][0], s[j0][1]);
                pf[1] = pack2h(s[j0][2], s[j0][3]);
                pf[2] = pack2h(s[j1][0], s[j1][1]);
                pf[3] = pack2h(s[j1][2], s[j1][3]);

                #pragma unroll
                for (int vp = 0; vp < 2; vp++) {
                    uint32_t vf[2][4];
                    #pragma unroll
                    for (int i = 0; i < 2; i++) {
                        const int np = vp * 2 + i;
                        const int g = lane >> 3;
                        const uint32_t vrow = sub * 64 + ks * 16 + (g & 1) * 8 + (lane & 7);
                        const uint32_t ro = vrow * RSTRIDE + np * 32 + (g >> 1) * 16;
                        ldsm4t(vf[i], kb + KOFF_V + ro);
                    }
                    #pragma unroll
                    for (int i = 0; i < 2; i++) {
                        const int np = vp * 2 + i;
                        mma_f16(acc_o[2 * np],     pf, vf[i][0], vf[i][1]);
                        mma_f16(acc_o[2 * np + 1], pf, vf[i][2], vf[i][3]);
                    }
                }
            }
        }
    }

    // ---- epilogue: normalize, write single fp16 [B*L, 1024] ----
    l0 += __shfl_xor_sync(0xffffffff, l0, 1);
    l0 += __shfl_xor_sync(0xffffffff, l0, 2);
    l1 += __shfl_xor_sync(0xffffffff, l1, 1);
    l1 += __shfl_xor_sync(0xffffffff, l1, 2);
    const float inv0 = 1.0f / l0, inv1 = 1.0f / l1;

    const size_t row0 = (size_t)(b * LL + q0 + wid * 16 + (lane >> 2));
    const size_t row1 = row0 + 8;
    const int colbase = h * HD + (lane & 3) * 2;
    #pragma unroll
    for (int j = 0; j < 8; j++) {
        const int col = colbase + j * 8;
        *(uint32_t*)(Of + row0 * DD + col) = pack2h(acc_o[j][0] * inv0, acc_o[j][1] * inv0);
        *(uint32_t*)(Of + row1 * DD + col) = pack2h(acc_o[j][2] * inv1, acc_o[j][3] * inv1);
    }
}

// -------------------------------------------------------------------------
extern "C" void kernel_launch(void* const* d_in, const int* in_sizes, int n_in,
                              void* d_out, int out_size)
{
    const float* x        = (const float*)d_in[0];
    const float* rope_cos = (const float*)d_in[1];
    const float* rope_sin = (const float*)d_in[2];
    const float* W_qkv    = (const float*)d_in[3];
    const float* W_out    = (const float*)d_in[4];
    const float* b_out    = (const float*)d_in[5];
    float* out = (float*)d_out;

    __half *xf, *wq, *wo, *attf, *Qf, *Kf, *Vf;
    cudaGetSymbolAddress((void**)&xf,   g_xf);
    cudaGetSymbolAddress((void**)&wq,   g_wqkvT);
    cudaGetSymbolAddress((void**)&wo,   g_woutT);
    cudaGetSymbolAddress((void**)&attf, g_attf);
    cudaGetSymbolAddress((void**)&Qf,   g_Qf);
    cudaGetSymbolAddress((void**)&Kf,   g_Kf);
    cudaGetSymbolAddress((void**)&Vf,   g_Vf);

    cudaFuncSetAttribute(flash_attn,    cudaFuncAttributeMaxDynamicSharedMemorySize, ATT_SMEM);
    cudaFuncSetAttribute(mma_gemm_qkv,  cudaFuncAttributeMaxDynamicSharedMemorySize, GEMM_SMEM);
    cudaFuncSetAttribute(mma_gemm_bias, cudaFuncAttributeMaxDynamicSharedMemorySize, GEMM_SMEM);

    // 0) fused operand conversion (x, W_qkvT, W_outT) in ONE launch
    conv_all<<<CONV_XBLKS + CONV_QBLKS + CONV_OBLKS, 256>>>(
        x, xf, W_qkv, wq, W_out, wo);

    // 1) QKV projection + fused RoPE epilogue -> Qf, Kf, Vf [B,H,L,HD]
    mma_gemm_qkv<<<dim3(NQKV / GBN, MROWS / GBM), 256, GEMM_SMEM>>>(
        xf, wq, rope_cos, rope_sin, Qf, Kf, Vf);

    // 2) flash attention (all single fp16, TK=128) -> attf
    flash_attn<<<dim3(LL / 128, BB * HH), 256, ATT_SMEM>>>(
        Qf, Kf, Vf, attf);

    // 3) output projection + bias
    mma_gemm_bias<<<dim3(DD / GBN, MROWS / GBM), 256, GEMM_SMEM>>>(
        attf, wo, b_out, out, DD, DD);
}